// round 7
// baseline (speedup 1.0000x reference)
#include <cuda_runtime.h>
#include <cuda_bf16.h>
#include <math.h>
#include <stdint.h>

// ---------------------------------------------------------------------------
// Problem constants
// ---------------------------------------------------------------------------
#define Bc    64
#define Tc    334
#define Fc    1024
#define Uc    1024
#define Ac    64
#define NBc   255
#define NTOK  (Bc * Tc)        // 21376 = 167 * 128
#define TM1   (Tc - 1)         // 333
#define NLOSS (Bc * TM1)       // 21312
#define LAM_C     0.95f
#define ACTENT_C  3e-4f
#define UNIMIX_A  0.00015625f  // 0.01 / 64
#define NCH   32               // K chunks of 32 (K = 1024)

// smem tile: 128 rows x 32 bf16, row stride 40 bf16 (80 B) -> conflict-free ldmatrix
#define TSTRIDE 40
#define TILE_B  (128 * TSTRIDE * 2)   // 10240 bytes
#define STAGE_B (4 * TILE_B)          // 40960 bytes (Ahi,Alo,Bhi,Blo)
#define NSTAGE  2
#define SMEM_B  (NSTAGE * STAGE_B)    // 81920 bytes -> 2 CTAs/SM

// ---------------------------------------------------------------------------
// Device scratch (per-net buffers for fused launches)
// ---------------------------------------------------------------------------
__device__ float g_h0v[(size_t)NTOK * Uc];
__device__ float g_h0s[(size_t)NTOK * Uc];
__device__ float g_h0p[(size_t)NTOK * Uc];
__device__ __nv_bfloat16 g_fhi[(size_t)NTOK * Uc];
__device__ __nv_bfloat16 g_flo[(size_t)NTOK * Uc];
__device__ __nv_bfloat16 g_ahi_v[(size_t)NTOK * Uc];
__device__ __nv_bfloat16 g_alo_v[(size_t)NTOK * Uc];
__device__ __nv_bfloat16 g_ahi_s[(size_t)NTOK * Uc];
__device__ __nv_bfloat16 g_alo_s[(size_t)NTOK * Uc];
__device__ __nv_bfloat16 g_ahi_p[(size_t)NTOK * Uc];
__device__ __nv_bfloat16 g_alo_p[(size_t)NTOK * Uc];
__device__ float g_vlog[(size_t)NTOK * NBc];
__device__ float g_slog[(size_t)NTOK * NBc];
__device__ float g_plog[(size_t)NTOK * Ac];
__device__ float g_smean[NTOK];
__device__ float g_ret[NLOSS];
__device__ float g_wgt[NLOSS];
__device__ float g_scale[4];
__device__ float g_loss[NLOSS];
// split K-major weights (bf16 hi/lo). Head pad rows never written -> stay 0.
__device__ __nv_bfloat16 g_wv_hi[5ull * 1024 * 1024];
__device__ __nv_bfloat16 g_wv_lo[5ull * 1024 * 1024];
__device__ __nv_bfloat16 g_ws_hi[5ull * 1024 * 1024];
__device__ __nv_bfloat16 g_ws_lo[5ull * 1024 * 1024];
__device__ __nv_bfloat16 g_wp_hi[5ull * 1024 * 1024];
__device__ __nv_bfloat16 g_wp_lo[5ull * 1024 * 1024];
__device__ __nv_bfloat16 g_hv_hi[256 * 1024];
__device__ __nv_bfloat16 g_hv_lo[256 * 1024];
__device__ __nv_bfloat16 g_hs_hi[256 * 1024];
__device__ __nv_bfloat16 g_hs_lo[256 * 1024];
__device__ __nv_bfloat16 g_hp_hi[128 * 1024];
__device__ __nv_bfloat16 g_hp_lo[128 * 1024];

// ---------------------------------------------------------------------------
// helpers
// ---------------------------------------------------------------------------
__device__ __forceinline__ uint32_t smem_u32(const void* p) {
    uint32_t a;
    asm("{ .reg .u64 t; cvta.to.shared.u64 t, %1; cvt.u32.u64 %0, t; }" : "=r"(a) : "l"(p));
    return a;
}
__device__ __forceinline__ void ldm_x4(uint32_t* f, uint32_t addr) {
    asm volatile("ldmatrix.sync.aligned.m8n8.x4.shared.b16 {%0,%1,%2,%3}, [%4];"
                 : "=r"(f[0]), "=r"(f[1]), "=r"(f[2]), "=r"(f[3]) : "r"(addr));
}
__device__ __forceinline__ void mma_bf16(float* c, const uint32_t* a,
                                         uint32_t b0, uint32_t b1) {
    asm volatile(
        "mma.sync.aligned.m16n8k16.row.col.f32.bf16.bf16.f32 "
        "{%0,%1,%2,%3}, {%4,%5,%6,%7}, {%8,%9}, {%0,%1,%2,%3};"
        : "+f"(c[0]), "+f"(c[1]), "+f"(c[2]), "+f"(c[3])
        : "r"(a[0]), "r"(a[1]), "r"(a[2]), "r"(a[3]), "r"(b0), "r"(b1));
}
__device__ __forceinline__ void cp16(uint32_t dst, const void* src) {
    asm volatile("cp.async.ca.shared.global [%0], [%1], 16;" :: "r"(dst), "l"(src));
}
__device__ __forceinline__ void cp_commit() {
    asm volatile("cp.async.commit_group;" ::: "memory");
}
__device__ __forceinline__ void cp_wait1() {
    asm volatile("cp.async.wait_group 1;" ::: "memory");
}
__device__ __forceinline__ void split1(float v, __nv_bfloat16& h, __nv_bfloat16& l) {
    h = __float2bfloat16(v);
    l = __float2bfloat16(v - __bfloat162float(h));
}

// select without dynamic param-array indexing (avoids local-mem struct copy)
#define SEL3(z, a, b, cc) ((z) == 0 ? (a) : (z) == 1 ? (b) : (cc))

// ---------------------------------------------------------------------------
// fused bf16x3-split tensor-core GEMM (up to 3 problems via blockIdx.z)
// scalar struct fields -> SEL chain, never a runtime-indexed param array.
// ---------------------------------------------------------------------------
struct GemmP {
    const __nv_bfloat16 *Ahi0, *Ahi1, *Ahi2;
    const __nv_bfloat16 *Alo0, *Alo1, *Alo2;
    const __nv_bfloat16 *Bhi0, *Bhi1, *Bhi2;
    const __nv_bfloat16 *Blo0, *Blo1, *Blo2;
    const float *bias0, *bias1, *bias2;
    float *C0, *C1, *C2;
};

__global__ __launch_bounds__(256, 2) void tc_gemm_f(GemmP P, int Mout)
{
    extern __shared__ char smem[];
    const uint32_t sb = smem_u32(smem);
    const int z = blockIdx.z;
    const __nv_bfloat16* __restrict__ Ahi = SEL3(z, P.Ahi0, P.Ahi1, P.Ahi2);
    const __nv_bfloat16* __restrict__ Alo = SEL3(z, P.Alo0, P.Alo1, P.Alo2);
    const __nv_bfloat16* __restrict__ Bhi = SEL3(z, P.Bhi0, P.Bhi1, P.Bhi2);
    const __nv_bfloat16* __restrict__ Blo = SEL3(z, P.Blo0, P.Blo1, P.Blo2);
    const float* __restrict__ bias = SEL3(z, P.bias0, P.bias1, P.bias2);
    float* __restrict__ C = SEL3(z, P.C0, P.C1, P.C2);

    const int tid = threadIdx.x;
    const int lane = tid & 31;
    const int warp = tid >> 5;
    const int brow = blockIdx.x * 128;
    const int bcol = blockIdx.y * 128;

    const int m0w = (warp >> 1) * 32;
    const int n0w = (warp & 1) * 64;
    const int lrow = lane & 15;
    const int lcol8 = (lane >> 4) << 3;

    float c[2][8][4];
    #pragma unroll
    for (int i = 0; i < 2; i++)
        #pragma unroll
        for (int j = 0; j < 8; j++)
            #pragma unroll
            for (int q = 0; q < 4; q++) c[i][j][q] = 0.f;

    auto issue = [&](int stage, int ch) {
        const int k0 = ch * 32;
        #pragma unroll
        for (int j = 0; j < 8; j++) {
            int gid = tid + 256 * j;
            int tl = gid >> 9;           // 0=Ahi 1=Alo 2=Bhi 3=Blo
            int t = gid & 511;
            int r = t >> 2, a = t & 3;
            const __nv_bfloat16* base =
                (tl == 0) ? Ahi : (tl == 1) ? Alo : (tl == 2) ? Bhi : Blo;
            int grow = ((tl < 2) ? brow : bcol) + r;
            const __nv_bfloat16* src = base + (size_t)grow * 1024 + k0 + a * 8;
            uint32_t dst = sb + (uint32_t)stage * STAGE_B + (uint32_t)tl * TILE_B
                         + (uint32_t)(r * 80 + a * 16);
            cp16(dst, src);
        }
        cp_commit();
    };

    issue(0, 0);
    issue(1, 1);

    for (int ch = 0; ch < NCH; ch++) {
        cp_wait1();
        __syncthreads();

        const uint32_t base = sb + (uint32_t)(ch & 1) * STAGE_B;
        #pragma unroll
        for (int ss = 0; ss < 2; ss++) {
            const int kk = ss * 16;
            uint32_t aHi[2][4], aLo[2][4], bH[4][4];
            #pragma unroll
            for (int i = 0; i < 2; i++) {
                uint32_t ar = base +
                    (uint32_t)((m0w + i * 16 + lrow) * TSTRIDE + kk + lcol8) * 2;
                ldm_x4(aHi[i], ar);
                ldm_x4(aLo[i], ar + TILE_B);
            }
            #pragma unroll
            for (int g = 0; g < 4; g++) {
                uint32_t br = base + 2 * TILE_B +
                    (uint32_t)((n0w + g * 16 + lrow) * TSTRIDE + kk + lcol8) * 2;
                ldm_x4(bH[g], br);
            }
            // pass 1: Ahi x Bhi (16 independent MMAs)
            #pragma unroll
            for (int g = 0; g < 4; g++)
                #pragma unroll
                for (int i = 0; i < 2; i++) {
                    mma_bf16(c[i][2 * g],     aHi[i], bH[g][0], bH[g][2]);
                    mma_bf16(c[i][2 * g + 1], aHi[i], bH[g][1], bH[g][3]);
                }
            // pass 2: Alo x Bhi
            #pragma unroll
            for (int g = 0; g < 4; g++)
                #pragma unroll
                for (int i = 0; i < 2; i++) {
                    mma_bf16(c[i][2 * g],     aLo[i], bH[g][0], bH[g][2]);
                    mma_bf16(c[i][2 * g + 1], aLo[i], bH[g][1], bH[g][3]);
                }
            // pass 3: Ahi x Blo (bL loaded just-in-time, reuses 4 regs)
            #pragma unroll
            for (int g = 0; g < 4; g++) {
                uint32_t bL[4];
                uint32_t br = base + 3 * TILE_B +
                    (uint32_t)((n0w + g * 16 + lrow) * TSTRIDE + kk + lcol8) * 2;
                ldm_x4(bL, br);
                #pragma unroll
                for (int i = 0; i < 2; i++) {
                    mma_bf16(c[i][2 * g],     aHi[i], bL[0], bL[2]);
                    mma_bf16(c[i][2 * g + 1], aHi[i], bL[1], bL[3]);
                }
            }
        }
        __syncthreads();
        if (ch + NSTAGE < NCH) issue(ch & 1, ch + NSTAGE);
        else cp_commit();
    }

    // epilogue
    const int r = lane >> 2;
    const int cc = 2 * (lane & 3);
    #pragma unroll
    for (int i = 0; i < 2; i++) {
        int rowb = brow + m0w + i * 16;
        #pragma unroll
        for (int j = 0; j < 8; j++) {
            int col = bcol + n0w + j * 8 + cc;
            float b0 = 0.f, b1 = 0.f;
            if (bias) {
                if (col < Mout) b0 = bias[col];
                if (col + 1 < Mout) b1 = bias[col + 1];
            }
            float* p0 = C + (size_t)(rowb + r) * Mout + col;
            float* p1 = C + (size_t)(rowb + r + 8) * Mout + col;
            if (col + 1 < Mout) {
                p0[0] = c[i][j][0] + b0; p0[1] = c[i][j][1] + b1;
                p1[0] = c[i][j][2] + b0; p1[1] = c[i][j][3] + b1;
            } else if (col < Mout) {
                p0[0] = c[i][j][0] + b0;
                p1[0] = c[i][j][2] + b0;
            }
        }
    }
}

// ---------------------------------------------------------------------------
// all 15 square weight transpose+splits in one launch (z = net*5 + layer)
// ---------------------------------------------------------------------------
struct WtP {
    const float *Win0, *Win1, *Win2;
    const float *Whid0, *Whid1, *Whid2;
    __nv_bfloat16 *Whi0, *Whi1, *Whi2;
    __nv_bfloat16 *Wlo0, *Wlo1, *Wlo2;
};

__global__ __launch_bounds__(256) void split_wt15_kernel(WtP P)
{
    __shared__ float t[32][33];
    int z = blockIdx.z;
    int net = z / 5, layer = z % 5;
    const float* Win  = SEL3(net, P.Win0, P.Win1, P.Win2);
    const float* Whid = SEL3(net, P.Whid0, P.Whid1, P.Whid2);
    __nv_bfloat16* Whi = SEL3(net, P.Whi0, P.Whi1, P.Whi2);
    __nv_bfloat16* Wlo = SEL3(net, P.Wlo0, P.Wlo1, P.Wlo2);
    const float* W = (layer == 0) ? Win : (Whid + (size_t)(layer - 1) * Uc * Uc);
    __nv_bfloat16* dhi = Whi + (size_t)layer * Uc * Uc;
    __nv_bfloat16* dlo = Wlo + (size_t)layer * Uc * Uc;
    int k0 = blockIdx.x * 32, m0 = blockIdx.y * 32;
    int x = threadIdx.x, y = threadIdx.y;   // 32 x 8
    #pragma unroll
    for (int j = 0; j < 32; j += 8)
        t[y + j][x] = W[(size_t)(k0 + y + j) * Uc + m0 + x];
    __syncthreads();
    #pragma unroll
    for (int j = 0; j < 32; j += 8) {
        int m = m0 + y + j;
        float v = t[x][y + j];
        __nv_bfloat16 h, l;
        split1(v, h, l);
        dhi[(size_t)m * 1024 + k0 + x] = h;
        dlo[(size_t)m * 1024 + k0 + x] = l;
    }
}

// head transpose + split: W[1024, M] -> [M,1024]
__global__ __launch_bounds__(256) void split_wt_kernel(
    const float* __restrict__ W, __nv_bfloat16* __restrict__ Whi,
    __nv_bfloat16* __restrict__ Wlo, int M)
{
    __shared__ float t[32][33];
    int k0 = blockIdx.x * 32, m0 = blockIdx.y * 32;
    int x = threadIdx.x, y = threadIdx.y;
    #pragma unroll
    for (int j = 0; j < 32; j += 8) {
        int m = m0 + x;
        if (m < M) t[y + j][x] = W[(size_t)(k0 + y + j) * M + m];
    }
    __syncthreads();
    #pragma unroll
    for (int j = 0; j < 32; j += 8) {
        int m = m0 + y + j;
        if (m < M) {
            float v = t[x][y + j];
            __nv_bfloat16 h, l;
            split1(v, h, l);
            Whi[(size_t)m * 1024 + k0 + x] = h;
            Wlo[(size_t)m * 1024 + k0 + x] = l;
        }
    }
}

// ---------------------------------------------------------------------------
// feat split
// ---------------------------------------------------------------------------
__global__ __launch_bounds__(256) void split_act_kernel(
    const float* __restrict__ X, __nv_bfloat16* __restrict__ Hi,
    __nv_bfloat16* __restrict__ Lo)
{
    size_t i = (size_t)blockIdx.x * 256 + threadIdx.x;
    float4 v = ((const float4*)X)[i];
    __nv_bfloat16 hx, hy, hz, hw, lx, ly, lz, lw;
    split1(v.x, hx, lx); split1(v.y, hy, ly);
    split1(v.z, hz, lz); split1(v.w, hw, lw);
    __nv_bfloat162 h0(hx, hy), h1(hz, hw), l0(lx, ly), l1(lz, lw);
    uint2 hp, lp;
    hp.x = *(uint32_t*)&h0; hp.y = *(uint32_t*)&h1;
    lp.x = *(uint32_t*)&l0; lp.y = *(uint32_t*)&l1;
    ((uint2*)Hi)[i] = hp;
    ((uint2*)Lo)[i] = lp;
}

// ---------------------------------------------------------------------------
// fused rmsnorm + silu + split for 3 nets (blockIdx.y = net)
// ---------------------------------------------------------------------------
__device__ __forceinline__ float silu_f(float z) { return z / (1.f + expf(-z)); }

struct RmsP {
    const float *X0, *X1, *X2;
    const float *g0, *g1, *g2;    // already offset to the layer row
    __nv_bfloat16 *Hi0, *Hi1, *Hi2;
    __nv_bfloat16 *Lo0, *Lo1, *Lo2;
};

__global__ __launch_bounds__(256) void rms3_kernel(RmsP P)
{
    int net = blockIdx.y;
    int row = blockIdx.x;
    int t = threadIdx.x;
    const float* X = SEL3(net, P.X0, P.X1, P.X2);
    const float* g = SEL3(net, P.g0, P.g1, P.g2);
    __nv_bfloat16* Hi = SEL3(net, P.Hi0, P.Hi1, P.Hi2);
    __nv_bfloat16* Lo = SEL3(net, P.Lo0, P.Lo1, P.Lo2);

    const float4* x4 = (const float4*)(X + (size_t)row * Uc);
    float4 xv = x4[t];
    float ss = xv.x * xv.x + xv.y * xv.y + xv.z * xv.z + xv.w * xv.w;
    #pragma unroll
    for (int o = 16; o; o >>= 1) ss += __shfl_xor_sync(0xffffffffu, ss, o);
    __shared__ float sh[8];
    if ((t & 31) == 0) sh[t >> 5] = ss;
    __syncthreads();
    if (t < 32) {
        float v = (t < 8) ? sh[t] : 0.f;
        #pragma unroll
        for (int o = 4; o; o >>= 1) v += __shfl_xor_sync(0xffffffffu, v, o);
        if (t == 0) sh[0] = v;
    }
    __syncthreads();
    float r = rsqrtf(sh[0] * (1.0f / (float)Uc) + 1e-6f);
    float4 gv = ((const float4*)g)[t];
    float4 o;
    o.x = silu_f(xv.x * r * gv.x);
    o.y = silu_f(xv.y * r * gv.y);
    o.z = silu_f(xv.z * r * gv.z);
    o.w = silu_f(xv.w * r * gv.w);
    __nv_bfloat16 hx, hy, hz, hw, lx, ly, lz, lw;
    split1(o.x, hx, lx); split1(o.y, hy, ly);
    split1(o.z, hz, lz); split1(o.w, hw, lw);
    __nv_bfloat162 h0(hx, hy), h1(hz, hw), l0(lx, ly), l1(lz, lw);
    uint2 hp, lp;
    hp.x = *(uint32_t*)&h0; hp.y = *(uint32_t*)&h1;
    lp.x = *(uint32_t*)&l0; lp.y = *(uint32_t*)&l1;
    ((uint2*)(Hi + (size_t)row * Uc))[t] = hp;
    ((uint2*)(Lo + (size_t)row * Uc))[t] = lp;
}

// ---------------------------------------------------------------------------
// symexp bins
// ---------------------------------------------------------------------------
__device__ __forceinline__ float bin_val(int i) {
    float u = -20.0f + (40.0f / 254.0f) * (float)i;
    return copysignf(expm1f(fabsf(u)), u);
}

// ---------------------------------------------------------------------------
// slow_mean
// ---------------------------------------------------------------------------
__global__ __launch_bounds__(256) void slowmean_kernel(
    const float* __restrict__ slog, float* __restrict__ smean)
{
    __shared__ float sred[8];
    __shared__ double dden[8], dnum[8];
    int row = blockIdx.x, tid = threadIdx.x;
    float lg = -3.4e38f, bn = 0.f;
    if (tid < NBc) {
        lg = slog[(size_t)row * NBc + tid];
        bn = bin_val(tid);
    }
    float m = lg;
    #pragma unroll
    for (int o = 16; o; o >>= 1) m = fmaxf(m, __shfl_xor_sync(0xffffffffu, m, o));
    if ((tid & 31) == 0) sred[tid >> 5] = m;
    __syncthreads();
    if (tid < 32) {
        float v = (tid < 8) ? sred[tid] : -3.4e38f;
        #pragma unroll
        for (int o = 4; o; o >>= 1) v = fmaxf(v, __shfl_xor_sync(0xffffffffu, v, o));
        if (tid == 0) sred[0] = v;
    }
    __syncthreads();
    float M = sred[0];
    float e = (tid < NBc) ? expf(lg - M) : 0.f;
    double den = (double)e;
    double num = (double)e * (double)bn;
    #pragma unroll
    for (int o = 16; o; o >>= 1) {
        den += __shfl_xor_sync(0xffffffffu, den, o);
        num += __shfl_xor_sync(0xffffffffu, num, o);
    }
    if ((tid & 31) == 0) { dden[tid >> 5] = den; dnum[tid >> 5] = num; }
    __syncthreads();
    if (tid == 0) {
        double D = 0, Nn = 0;
        #pragma unroll
        for (int i = 0; i < 8; i++) { D += dden[i]; Nn += dnum[i]; }
        smean[row] = (float)(Nn / D);
    }
}

// ---------------------------------------------------------------------------
// lambda-return scan
// ---------------------------------------------------------------------------
__global__ void lamret_kernel(
    const float* __restrict__ reward, const float* __restrict__ cont,
    const float* __restrict__ smean, float* __restrict__ ret, float* __restrict__ wgt)
{
    int b = threadIdx.x;
    if (b >= Bc) return;
    float acc = 1.f;
    for (int t = 0; t < TM1; t++) {
        acc *= cont[b * Tc + t];
        wgt[b * TM1 + t] = acc;
    }
    float r = smean[b * Tc + (Tc - 1)];
    for (int t = TM1 - 1; t >= 0; t--) {
        float live = cont[b * Tc + t + 1];
        float interm = reward[b * Tc + t + 1] + (1.f - LAM_C) * live * smean[b * Tc + t + 1];
        r = interm + live * LAM_C * r;
        ret[b * TM1 + t] = r;
    }
}

// ---------------------------------------------------------------------------
// percentile via bitonic sort
// ---------------------------------------------------------------------------
__global__ void percentile_kernel(const float* __restrict__ ret, float* __restrict__ scale)
{
    extern __shared__ float s[];
    const int PAD = 32768;
    for (int i = threadIdx.x; i < PAD; i += blockDim.x)
        s[i] = (i < NLOSS) ? ret[i] : 3.4e38f;
    __syncthreads();
    for (int ksz = 2; ksz <= PAD; ksz <<= 1) {
        for (int j = ksz >> 1; j > 0; j >>= 1) {
            for (int a = threadIdx.x; a < PAD; a += blockDim.x) {
                int p = a ^ j;
                if (p > a) {
                    bool asc = ((a & ksz) == 0);
                    float x = s[a], y = s[p];
                    if ((x > y) == asc) { s[a] = y; s[p] = x; }
                }
            }
            __syncthreads();
        }
    }
    if (threadIdx.x == 0) {
        double p5 = 0.05 * (double)(NLOSS - 1);
        double p95 = 0.95 * (double)(NLOSS - 1);
        int i5 = (int)p5, i95 = (int)p95;
        float f5 = (float)(p5 - i5), f95 = (float)(p95 - i95);
        float lo = s[i5] + f5 * (s[i5 + 1] - s[i5]);
        float hi = s[i95] + f95 * (s[i95 + 1] - s[i95]);
        scale[0] = lo;
        scale[1] = hi;
        scale[2] = fmaxf(hi - lo, 1.0f);
    }
}

// ---------------------------------------------------------------------------
// per-token loss
// ---------------------------------------------------------------------------
__device__ __forceinline__ float twohot_nll(const float* svl, const float* sbins,
                                            float logZ, float y)
{
    y = fminf(fmaxf(y, sbins[0]), sbins[NBc - 1]);
    int lo = 0, hi = NBc - 1;
    while (hi > lo) {
        int mid = (lo + hi) >> 1;
        if (sbins[mid] >= y) hi = mid; else lo = mid + 1;
    }
    int k = hi - 1;
    if (k < 0) k = 0;
    if (k > NBc - 2) k = NBc - 2;
    float bl = sbins[k], bh = sbins[k + 1];
    float w = (y - bl) / (bh - bl);
    w = fminf(fmaxf(w, 0.f), 1.f);
    float l0 = svl[k] - logZ, l1 = svl[k + 1] - logZ;
    return -((1.f - w) * l0 + w * l1);
}

__global__ __launch_bounds__(256) void loss_kernel(
    const float* __restrict__ vlog, const float* __restrict__ plog,
    const float* __restrict__ smean, const float* __restrict__ ret,
    const float* __restrict__ wgt, const int* __restrict__ act,
    const float* __restrict__ scale, float* __restrict__ loss)
{
    __shared__ float sbins[NBc];
    __shared__ float svl[NBc];
    __shared__ float sred[8];
    __shared__ float sres[4];

    int i = blockIdx.x;
    int b = i / TM1, t = i - b * TM1;
    int row = b * Tc + t;
    int tid = threadIdx.x;

    if (tid < NBc) {
        sbins[tid] = bin_val(tid);
        svl[tid] = vlog[(size_t)row * NBc + tid];
    }
    __syncthreads();

    float v = (tid < NBc) ? svl[tid] : -3.4e38f;
    #pragma unroll
    for (int o = 16; o; o >>= 1) v = fmaxf(v, __shfl_xor_sync(0xffffffffu, v, o));
    if ((tid & 31) == 0) sred[tid >> 5] = v;
    __syncthreads();
    if (tid < 32) {
        float m = (tid < 8) ? sred[tid] : -3.4e38f;
        #pragma unroll
        for (int o = 4; o; o >>= 1) m = fmaxf(m, __shfl_xor_sync(0xffffffffu, m, o));
        if (tid == 0) sres[0] = m;
    }
    __syncthreads();
    float M = sres[0];
    float e = (tid < NBc) ? expf(svl[tid] - M) : 0.f;
    #pragma unroll
    for (int o = 16; o; o >>= 1) e += __shfl_xor_sync(0xffffffffu, e, o);
    if ((tid & 31) == 0) sred[tid >> 5] = e;
    __syncthreads();
    if (tid < 32) {
        float s = (tid < 8) ? sred[tid] : 0.f;
        #pragma unroll
        for (int o = 4; o; o >>= 1) s += __shfl_xor_sync(0xffffffffu, s, o);
        if (tid == 0) sres[0] = M + logf(s);
    }
    __syncthreads();
    float logZ = sres[0];

    if (tid < 32) {
        float p0 = plog[(size_t)row * Ac + tid];
        float p1 = plog[(size_t)row * Ac + tid + 32];
        float m = fmaxf(p0, p1);
        #pragma unroll
        for (int o = 16; o; o >>= 1) m = fmaxf(m, __shfl_xor_sync(0xffffffffu, m, o));
        float e0 = expf(p0 - m), e1 = expf(p1 - m);
        float s = e0 + e1;
        #pragma unroll
        for (int o = 16; o; o >>= 1) s += __shfl_xor_sync(0xffffffffu, s, o);
        float inv = 1.0f / s;
        float pr0 = 0.99f * e0 * inv + UNIMIX_A;
        float pr1 = 0.99f * e1 * inv + UNIMIX_A;
        float lp0 = logf(pr0), lp1 = logf(pr1);
        float entp = -(pr0 * lp0 + pr1 * lp1);
        #pragma unroll
        for (int o = 16; o; o >>= 1) entp += __shfl_xor_sync(0xffffffffu, entp, o);
        int a = act[row];
        float lpi = (a == tid) ? lp0 : ((a == tid + 32) ? lp1 : 0.f);
        #pragma unroll
        for (int o = 16; o; o >>= 1) lpi += __shfl_xor_sync(0xffffffffu, lpi, o);
        if (tid == 0) { sres[1] = entp; sres[2] = lpi; }
    }
    __syncthreads();

    if (tid == 0) {
        float reti = ret[i];
        float sm = smean[row];
        float rscale = scale[2];
        float adv = (reti - sm) / rscale;
        float wt = wgt[i];
        float pl = wt * -(sres[2] * adv + ACTENT_C * sres[1]);
        float vl = twohot_nll(svl, sbins, logZ, reti) + twohot_nll(svl, sbins, logZ, sm);
        loss[i] = pl + wt * vl;
    }
}

// ---------------------------------------------------------------------------
// final reduction
// ---------------------------------------------------------------------------
__global__ __launch_bounds__(1024) void reduce_kernel(
    const float* __restrict__ loss, float* __restrict__ out)
{
    __shared__ double sd[32];
    double s = 0.0;
    for (int i = threadIdx.x; i < NLOSS; i += 1024) s += (double)loss[i];
    #pragma unroll
    for (int o = 16; o; o >>= 1) s += __shfl_xor_sync(0xffffffffu, s, o);
    if ((threadIdx.x & 31) == 0) sd[threadIdx.x >> 5] = s;
    __syncthreads();
    if (threadIdx.x == 0) {
        double tot = 0.0;
        #pragma unroll
        for (int w = 0; w < 32; w++) tot += sd[w];
        out[0] = (float)(tot / (double)NLOSS);
    }
}

// ---------------------------------------------------------------------------
// host
// ---------------------------------------------------------------------------
extern "C" void kernel_launch(void* const* d_in, const int* in_sizes, int n_in,
                              void* d_out, int out_size)
{
    const float* feat   = (const float*)d_in[0];
    const float* reward = (const float*)d_in[1];
    const float* cont   = (const float*)d_in[2];
    const int*   act    = (const int*)  d_in[3];
    const float* pW_in  = (const float*)d_in[4];
    const float* pW_hid = (const float*)d_in[5];
    const float* p_gn   = (const float*)d_in[6];
    const float* pHw    = (const float*)d_in[7];
    const float* pHb    = (const float*)d_in[8];
    const float* vW_in  = (const float*)d_in[9];
    const float* vW_hid = (const float*)d_in[10];
    const float* v_gn   = (const float*)d_in[11];
    const float* vHw    = (const float*)d_in[12];
    const float* vHb    = (const float*)d_in[13];
    const float* sW_in  = (const float*)d_in[14];
    const float* sW_hid = (const float*)d_in[15];
    const float* s_gn   = (const float*)d_in[16];
    const float* sHw    = (const float*)d_in[17];
    const float* sHb    = (const float*)d_in[18];

    float *h0[3], *vlog, *slog, *plg, *smean, *ret, *wgt, *scale, *loss;
    __nv_bfloat16 *fhi, *flo;
    __nv_bfloat16 *ahi[3], *alo[3], *whi[3], *wlo[3], *hhi[3], *hlo[3];
    cudaGetSymbolAddress((void**)&h0[0], g_h0v);
    cudaGetSymbolAddress((void**)&h0[1], g_h0s);
    cudaGetSymbolAddress((void**)&h0[2], g_h0p);
    cudaGetSymbolAddress((void**)&fhi, g_fhi);
    cudaGetSymbolAddress((void**)&flo, g_flo);
    cudaGetSymbolAddress((void**)&ahi[0], g_ahi_v);
    cudaGetSymbolAddress((void**)&alo[0], g_alo_v);
    cudaGetSymbolAddress((void**)&ahi[1], g_ahi_s);
    cudaGetSymbolAddress((void**)&alo[1], g_alo_s);
    cudaGetSymbolAddress((void**)&ahi[2], g_ahi_p);
    cudaGetSymbolAddress((void**)&alo[2], g_alo_p);
    cudaGetSymbolAddress((void**)&vlog, g_vlog);
    cudaGetSymbolAddress((void**)&slog, g_slog);
    cudaGetSymbolAddress((void**)&plg, g_plog);
    cudaGetSymbolAddress((void**)&smean, g_smean);
    cudaGetSymbolAddress((void**)&ret, g_ret);
    cudaGetSymbolAddress((void**)&wgt, g_wgt);
    cudaGetSymbolAddress((void**)&scale, g_scale);
    cudaGetSymbolAddress((void**)&loss, g_loss);
    cudaGetSymbolAddress((void**)&whi[0], g_wv_hi);
    cudaGetSymbolAddress((void**)&wlo[0], g_wv_lo);
    cudaGetSymbolAddress((void**)&whi[1], g_ws_hi);
    cudaGetSymbolAddress((void**)&wlo[1], g_ws_lo);
    cudaGetSymbolAddress((void**)&whi[2], g_wp_hi);
    cudaGetSymbolAddress((void**)&wlo[2], g_wp_lo);
    cudaGetSymbolAddress((void**)&hhi[0], g_hv_hi);
    cudaGetSymbolAddress((void**)&hlo[0], g_hv_lo);
    cudaGetSymbolAddress((void**)&hhi[1], g_hs_hi);
    cudaGetSymbolAddress((void**)&hlo[1], g_hs_lo);
    cudaGetSymbolAddress((void**)&hhi[2], g_hp_hi);
    cudaGetSymbolAddress((void**)&hlo[2], g_hp_lo);

    cudaFuncSetAttribute(tc_gemm_f, cudaFuncAttributeMaxDynamicSharedMemorySize, SMEM_B);
    cudaFuncSetAttribute(percentile_kernel,
                         cudaFuncAttributeMaxDynamicSharedMemorySize, 131072);

    const float* gn[3] = {v_gn, s_gn, p_gn};

    dim3 tb(32, 8);
    // prep: 0=wt15, 1-3=head splits, 4=act split, 5=layer0 GEMM (ncu -s 5)
    WtP wp;
    wp.Win0 = vW_in;  wp.Whid0 = vW_hid;
    wp.Win1 = sW_in;  wp.Whid1 = sW_hid;
    wp.Win2 = pW_in;  wp.Whid2 = pW_hid;
    wp.Whi0 = whi[0]; wp.Wlo0 = wlo[0];
    wp.Whi1 = whi[1]; wp.Wlo1 = wlo[1];
    wp.Whi2 = whi[2]; wp.Wlo2 = wlo[2];
    split_wt15_kernel<<<dim3(32, 32, 15), tb>>>(wp);
    split_wt_kernel<<<dim3(32, 8), tb>>>(vHw, hhi[0], hlo[0], NBc);
    split_wt_kernel<<<dim3(32, 8), tb>>>(sHw, hhi[1], hlo[1], NBc);
    split_wt_kernel<<<dim3(32, 2), tb>>>(pHw, hhi[2], hlo[2], Ac);
    split_act_kernel<<<NTOK, 256>>>(feat, fhi, flo);

    // 5 fused layer GEMMs (z = net) + fused rmsnorm
    for (int l = 0; l < 5; l++) {
        GemmP P;
        const __nv_bfloat16* ai[3];
        const __nv_bfloat16* al[3];
        for (int n = 0; n < 3; n++) {
            ai[n] = (l == 0) ? fhi : ahi[n];
            al[n] = (l == 0) ? flo : alo[n];
        }
        P.Ahi0 = ai[0]; P.Ahi1 = ai[1]; P.Ahi2 = ai[2];
        P.Alo0 = al[0]; P.Alo1 = al[1]; P.Alo2 = al[2];
        P.Bhi0 = whi[0] + (size_t)l * Uc * Uc;
        P.Bhi1 = whi[1] + (size_t)l * Uc * Uc;
        P.Bhi2 = whi[2] + (size_t)l * Uc * Uc;
        P.Blo0 = wlo[0] + (size_t)l * Uc * Uc;
        P.Blo1 = wlo[1] + (size_t)l * Uc * Uc;
        P.Blo2 = wlo[2] + (size_t)l * Uc * Uc;
        P.bias0 = P.bias1 = P.bias2 = nullptr;
        P.C0 = h0[0]; P.C1 = h0[1]; P.C2 = h0[2];
        tc_gemm_f<<<dim3(NTOK / 128, 8, 3), 256, SMEM_B>>>(P, Uc);

        RmsP R;
        R.X0 = h0[0]; R.X1 = h0[1]; R.X2 = h0[2];
        R.g0 = gn[0] + (size_t)l * Uc;
        R.g1 = gn[1] + (size_t)l * Uc;
        R.g2 = gn[2] + (size_t)l * Uc;
        R.Hi0 = ahi[0]; R.Hi1 = ahi[1]; R.Hi2 = ahi[2];
        R.Lo0 = alo[0]; R.Lo1 = alo[1]; R.Lo2 = alo[2];
        rms3_kernel<<<dim3(NTOK, 3), 256>>>(R);
    }

    // heads: v+s fused (Mout=255, 2 col tiles), p separate (Mout=64, 1 tile)
    {
        GemmP P;
        P.Ahi0 = ahi[0]; P.Alo0 = alo[0]; P.Bhi0 = hhi[0]; P.Blo0 = hlo[0];
        P.Ahi1 = ahi[1]; P.Alo1 = alo[1]; P.Bhi1 = hhi[1]; P.Blo1 = hlo[1];
        P.Ahi2 = ahi[0]; P.Alo2 = alo[0]; P.Bhi2 = hhi[0]; P.Blo2 = hlo[0];
        P.bias0 = vHb; P.bias1 = sHb; P.bias2 = nullptr;
        P.C0 = vlog;   P.C1 = slog;   P.C2 = nullptr;
        tc_gemm_f<<<dim3(NTOK / 128, 2, 2), 256, SMEM_B>>>(P, NBc);
    }
    {
        GemmP P;
        P.Ahi0 = ahi[2]; P.Alo0 = alo[2]; P.Bhi0 = hhi[2]; P.Blo0 = hlo[2];
        P.Ahi1 = ahi[2]; P.Alo1 = alo[2]; P.Bhi1 = hhi[2]; P.Blo1 = hlo[2];
        P.Ahi2 = ahi[2]; P.Alo2 = alo[2]; P.Bhi2 = hhi[2]; P.Blo2 = hlo[2];
        P.bias0 = pHb; P.bias1 = nullptr; P.bias2 = nullptr;
        P.C0 = plg;    P.C1 = nullptr;    P.C2 = nullptr;
        tc_gemm_f<<<dim3(NTOK / 128, 1, 1), 256, SMEM_B>>>(P, Ac);
    }

    slowmean_kernel<<<NTOK, 256>>>(slog, smean);
    lamret_kernel<<<1, 64>>>(reward, cont, smean, ret, wgt);
    percentile_kernel<<<1, 1024, 131072>>>(ret, scale);
    loss_kernel<<<NLOSS, 256>>>(vlog, plg, smean, ret, wgt, act, scale, loss);
    reduce_kernel<<<1, 1024>>>(loss, (float*)d_out);
}

// round 8
// speedup vs baseline: 1.5103x; 1.5103x over previous
#include <cuda_runtime.h>
#include <cuda_bf16.h>
#include <math.h>
#include <stdint.h>

// ---------------------------------------------------------------------------
// Problem constants
// ---------------------------------------------------------------------------
#define Bc    64
#define Tc    334
#define Fc    1024
#define Uc    1024
#define Ac    64
#define NBc   255
#define NTOK  (Bc * Tc)        // 21376 = 167 * 128
#define TM1   (Tc - 1)         // 333
#define NLOSS (Bc * TM1)       // 21312
#define LAM_C     0.95f
#define ACTENT_C  3e-4f
#define UNIMIX_A  0.00015625f  // 0.01 / 64
#define NCH   32               // K chunks of 32 (K = 1024)

// smem tile: 128 rows x 32 bf16, row stride 40 bf16 (80 B) -> conflict-free ldmatrix
#define TSTRIDE 40
#define TILE_B  (128 * TSTRIDE * 2)   // 10240 bytes
#define STAGE_B (4 * TILE_B)          // 40960 bytes (Ahi,Alo,Bhi,Blo)
#define NSTAGE  2
#define SMEM_B  (NSTAGE * STAGE_B)    // 81920 bytes -> 2 CTAs/SM

// net strides (elements)
#define ASTR ((size_t)NTOK * Uc)          // activation buffers
#define WSTR ((size_t)5 * 1024 * 1024)    // square-weight buffers
#define HSTR ((size_t)256 * 1024)         // v/s head weight buffers
#define LSTR ((size_t)NTOK * NBc)         // v/s logits

// ---------------------------------------------------------------------------
// Device scratch — single symbols, net index via stride
// ---------------------------------------------------------------------------
__device__ float g_h0[3 * ASTR];
__device__ __nv_bfloat16 g_fhi[ASTR];
__device__ __nv_bfloat16 g_flo[ASTR];
__device__ __nv_bfloat16 g_a_hi[3 * ASTR];
__device__ __nv_bfloat16 g_a_lo[3 * ASTR];
__device__ float g_vslog[2 * LSTR];          // [0]=vlog, [1]=slog
__device__ float g_plog[(size_t)NTOK * Ac];
__device__ float g_smean[NTOK];
__device__ float g_ret[NLOSS];
__device__ float g_wgt[NLOSS];
__device__ float g_scale[4];
__device__ float g_loss[NLOSS];
// split K-major weights (bf16 hi/lo). Head pad rows never written -> stay 0.
__device__ __nv_bfloat16 g_w_hi[3 * WSTR];
__device__ __nv_bfloat16 g_w_lo[3 * WSTR];
__device__ __nv_bfloat16 g_hvs_hi[2 * HSTR];
__device__ __nv_bfloat16 g_hvs_lo[2 * HSTR];
__device__ __nv_bfloat16 g_hp_hi[128 * 1024];
__device__ __nv_bfloat16 g_hp_lo[128 * 1024];

// ---------------------------------------------------------------------------
// helpers
// ---------------------------------------------------------------------------
__device__ __forceinline__ uint32_t smem_u32(const void* p) {
    uint32_t a;
    asm("{ .reg .u64 t; cvta.to.shared.u64 t, %1; cvt.u32.u64 %0, t; }" : "=r"(a) : "l"(p));
    return a;
}
__device__ __forceinline__ void ldm_x4(uint32_t* f, uint32_t addr) {
    asm volatile("ldmatrix.sync.aligned.m8n8.x4.shared.b16 {%0,%1,%2,%3}, [%4];"
                 : "=r"(f[0]), "=r"(f[1]), "=r"(f[2]), "=r"(f[3]) : "r"(addr));
}
__device__ __forceinline__ void mma_bf16(float* c, const uint32_t* a,
                                         uint32_t b0, uint32_t b1) {
    asm volatile(
        "mma.sync.aligned.m16n8k16.row.col.f32.bf16.bf16.f32 "
        "{%0,%1,%2,%3}, {%4,%5,%6,%7}, {%8,%9}, {%0,%1,%2,%3};"
        : "+f"(c[0]), "+f"(c[1]), "+f"(c[2]), "+f"(c[3])
        : "r"(a[0]), "r"(a[1]), "r"(a[2]), "r"(a[3]), "r"(b0), "r"(b1));
}
__device__ __forceinline__ void cp16(uint32_t dst, const void* src) {
    asm volatile("cp.async.ca.shared.global [%0], [%1], 16;" :: "r"(dst), "l"(src));
}
__device__ __forceinline__ void cp_commit() {
    asm volatile("cp.async.commit_group;" ::: "memory");
}
__device__ __forceinline__ void cp_wait1() {
    asm volatile("cp.async.wait_group 1;" ::: "memory");
}
__device__ __forceinline__ void split1(float v, __nv_bfloat16& h, __nv_bfloat16& l) {
    h = __float2bfloat16(v);
    l = __float2bfloat16(v - __bfloat162float(h));
}
#define SEL3(z, a, b, cc) ((z) == 0 ? (a) : (z) == 1 ? (b) : (cc))

// ---------------------------------------------------------------------------
// bf16x3-split tensor-core GEMM (multi-problem via blockIdx.z + strides).
// Inner loop identical to the validated R5 kernel.
// ---------------------------------------------------------------------------
__global__ __launch_bounds__(256, 2) void tc_gemm(
    const __nv_bfloat16* __restrict__ Ahi_, const __nv_bfloat16* __restrict__ Alo_,
    size_t aStr,
    const __nv_bfloat16* __restrict__ Bhi_, const __nv_bfloat16* __restrict__ Blo_,
    size_t bStr,
    const float* bias0, const float* bias1,
    float* C_, size_t cStr, int Mout)
{
    extern __shared__ char smem[];
    const uint32_t sb = smem_u32(smem);
    const int z = blockIdx.z;
    const __nv_bfloat16* __restrict__ Ahi = Ahi_ + (size_t)z * aStr;
    const __nv_bfloat16* __restrict__ Alo = Alo_ + (size_t)z * aStr;
    const __nv_bfloat16* __restrict__ Bhi = Bhi_ + (size_t)z * bStr;
    const __nv_bfloat16* __restrict__ Blo = Blo_ + (size_t)z * bStr;
    const float* bias = (z == 0) ? bias0 : bias1;
    float* __restrict__ C = C_ + (size_t)z * cStr;

    const int tid = threadIdx.x;
    const int lane = tid & 31;
    const int warp = tid >> 5;
    const int brow = blockIdx.x * 128;
    const int bcol = blockIdx.y * 128;

    const int m0w = (warp >> 1) * 32;
    const int n0w = (warp & 1) * 64;
    const int lrow = lane & 15;
    const int lcol8 = (lane >> 4) << 3;

    float c[2][8][4];
    #pragma unroll
    for (int i = 0; i < 2; i++)
        #pragma unroll
        for (int j = 0; j < 8; j++)
            #pragma unroll
            for (int q = 0; q < 4; q++) c[i][j][q] = 0.f;

    auto issue = [&](int stage, int ch) {
        const int k0 = ch * 32;
        #pragma unroll
        for (int j = 0; j < 8; j++) {
            int gid = tid + 256 * j;
            int tl = gid >> 9;           // 0=Ahi 1=Alo 2=Bhi 3=Blo
            int t = gid & 511;
            int r = t >> 2, a = t & 3;
            const __nv_bfloat16* base =
                (tl == 0) ? Ahi : (tl == 1) ? Alo : (tl == 2) ? Bhi : Blo;
            int grow = ((tl < 2) ? brow : bcol) + r;
            const __nv_bfloat16* src = base + (size_t)grow * 1024 + k0 + a * 8;
            uint32_t dst = sb + (uint32_t)stage * STAGE_B + (uint32_t)tl * TILE_B
                         + (uint32_t)(r * 80 + a * 16);
            cp16(dst, src);
        }
        cp_commit();
    };

    issue(0, 0);
    issue(1, 1);

    for (int ch = 0; ch < NCH; ch++) {
        cp_wait1();
        __syncthreads();

        const uint32_t base = sb + (uint32_t)(ch & 1) * STAGE_B;
        #pragma unroll
        for (int ss = 0; ss < 2; ss++) {
            const int kk = ss * 16;
            uint32_t aHi[2][4], aLo[2][4], bH[4][4];
            #pragma unroll
            for (int i = 0; i < 2; i++) {
                uint32_t ar = base +
                    (uint32_t)((m0w + i * 16 + lrow) * TSTRIDE + kk + lcol8) * 2;
                ldm_x4(aHi[i], ar);
                ldm_x4(aLo[i], ar + TILE_B);
            }
            #pragma unroll
            for (int g = 0; g < 4; g++) {
                uint32_t br = base + 2 * TILE_B +
                    (uint32_t)((n0w + g * 16 + lrow) * TSTRIDE + kk + lcol8) * 2;
                ldm_x4(bH[g], br);
            }
            // pass 1: Ahi x Bhi (16 independent MMAs)
            #pragma unroll
            for (int g = 0; g < 4; g++)
                #pragma unroll
                for (int i = 0; i < 2; i++) {
                    mma_bf16(c[i][2 * g],     aHi[i], bH[g][0], bH[g][2]);
                    mma_bf16(c[i][2 * g + 1], aHi[i], bH[g][1], bH[g][3]);
                }
            // pass 2: Alo x Bhi
            #pragma unroll
            for (int g = 0; g < 4; g++)
                #pragma unroll
                for (int i = 0; i < 2; i++) {
                    mma_bf16(c[i][2 * g],     aLo[i], bH[g][0], bH[g][2]);
                    mma_bf16(c[i][2 * g + 1], aLo[i], bH[g][1], bH[g][3]);
                }
            // pass 3: Ahi x Blo (bL loaded just-in-time, reuses 4 regs)
            #pragma unroll
            for (int g = 0; g < 4; g++) {
                uint32_t bL[4];
                uint32_t br = base + 3 * TILE_B +
                    (uint32_t)((n0w + g * 16 + lrow) * TSTRIDE + kk + lcol8) * 2;
                ldm_x4(bL, br);
                #pragma unroll
                for (int i = 0; i < 2; i++) {
                    mma_bf16(c[i][2 * g],     aHi[i], bL[0], bL[2]);
                    mma_bf16(c[i][2 * g + 1], aHi[i], bL[1], bL[3]);
                }
            }
        }
        __syncthreads();
        if (ch + NSTAGE < NCH) issue(ch & 1, ch + NSTAGE);
        else cp_commit();
    }

    // epilogue
    const int r = lane >> 2;
    const int cc = 2 * (lane & 3);
    #pragma unroll
    for (int i = 0; i < 2; i++) {
        int rowb = brow + m0w + i * 16;
        #pragma unroll
        for (int j = 0; j < 8; j++) {
            int col = bcol + n0w + j * 8 + cc;
            float b0 = 0.f, b1 = 0.f;
            if (bias) {
                if (col < Mout) b0 = bias[col];
                if (col + 1 < Mout) b1 = bias[col + 1];
            }
            float* p0 = C + (size_t)(rowb + r) * Mout + col;
            float* p1 = C + (size_t)(rowb + r + 8) * Mout + col;
            if (col + 1 < Mout) {
                p0[0] = c[i][j][0] + b0; p0[1] = c[i][j][1] + b1;
                p1[0] = c[i][j][2] + b0; p1[1] = c[i][j][3] + b1;
            } else if (col < Mout) {
                p0[0] = c[i][j][0] + b0;
                p1[0] = c[i][j][2] + b0;
            }
        }
    }
}

// ---------------------------------------------------------------------------
// all 15 square weight transpose+splits in one launch (z = net*5 + layer)
// outputs go into the single strided symbols -> only 2 output pointers
// ---------------------------------------------------------------------------
__global__ __launch_bounds__(256) void split_wt15_kernel(
    const float* Win0, const float* Win1, const float* Win2,
    const float* Whid0, const float* Whid1, const float* Whid2,
    __nv_bfloat16* Whi, __nv_bfloat16* Wlo)
{
    __shared__ float t[32][33];
    int z = blockIdx.z;
    int net = z / 5, layer = z % 5;
    const float* Win  = SEL3(net, Win0, Win1, Win2);
    const float* Whid = SEL3(net, Whid0, Whid1, Whid2);
    const float* W = (layer == 0) ? Win : (Whid + (size_t)(layer - 1) * Uc * Uc);
    __nv_bfloat16* dhi = Whi + (size_t)net * WSTR + (size_t)layer * Uc * Uc;
    __nv_bfloat16* dlo = Wlo + (size_t)net * WSTR + (size_t)layer * Uc * Uc;
    int k0 = blockIdx.x * 32, m0 = blockIdx.y * 32;
    int x = threadIdx.x, y = threadIdx.y;   // 32 x 8
    #pragma unroll
    for (int j = 0; j < 32; j += 8)
        t[y + j][x] = W[(size_t)(k0 + y + j) * Uc + m0 + x];
    __syncthreads();
    #pragma unroll
    for (int j = 0; j < 32; j += 8) {
        int m = m0 + y + j;
        float v = t[x][y + j];
        __nv_bfloat16 h, l;
        split1(v, h, l);
        dhi[(size_t)m * 1024 + k0 + x] = h;
        dlo[(size_t)m * 1024 + k0 + x] = l;
    }
}

// head transpose + split: W[1024, M] -> [M,1024]
__global__ __launch_bounds__(256) void split_wt_kernel(
    const float* __restrict__ W, __nv_bfloat16* __restrict__ Whi,
    __nv_bfloat16* __restrict__ Wlo, int M)
{
    __shared__ float t[32][33];
    int k0 = blockIdx.x * 32, m0 = blockIdx.y * 32;
    int x = threadIdx.x, y = threadIdx.y;
    #pragma unroll
    for (int j = 0; j < 32; j += 8) {
        int m = m0 + x;
        if (m < M) t[y + j][x] = W[(size_t)(k0 + y + j) * M + m];
    }
    __syncthreads();
    #pragma unroll
    for (int j = 0; j < 32; j += 8) {
        int m = m0 + y + j;
        if (m < M) {
            float v = t[x][y + j];
            __nv_bfloat16 h, l;
            split1(v, h, l);
            Whi[(size_t)m * 1024 + k0 + x] = h;
            Wlo[(size_t)m * 1024 + k0 + x] = l;
        }
    }
}

// ---------------------------------------------------------------------------
// feat split
// ---------------------------------------------------------------------------
__global__ __launch_bounds__(256) void split_act_kernel(
    const float* __restrict__ X, __nv_bfloat16* __restrict__ Hi,
    __nv_bfloat16* __restrict__ Lo)
{
    size_t i = (size_t)blockIdx.x * 256 + threadIdx.x;
    float4 v = ((const float4*)X)[i];
    __nv_bfloat16 hx, hy, hz, hw, lx, ly, lz, lw;
    split1(v.x, hx, lx); split1(v.y, hy, ly);
    split1(v.z, hz, lz); split1(v.w, hw, lw);
    __nv_bfloat162 h0(hx, hy), h1(hz, hw), l0(lx, ly), l1(lz, lw);
    uint2 hp, lp;
    hp.x = *(uint32_t*)&h0; hp.y = *(uint32_t*)&h1;
    lp.x = *(uint32_t*)&l0; lp.y = *(uint32_t*)&l1;
    ((uint2*)Hi)[i] = hp;
    ((uint2*)Lo)[i] = lp;
}

// ---------------------------------------------------------------------------
// fused rmsnorm + silu + split for 3 nets (blockIdx.y = net, strided buffers)
// ---------------------------------------------------------------------------
__device__ __forceinline__ float silu_f(float z) { return z / (1.f + expf(-z)); }

__global__ __launch_bounds__(256) void rms3_kernel(
    const float* __restrict__ X,            // g_h0 base
    const float* g0, const float* g1, const float* g2,  // per-net gain rows
    __nv_bfloat16* __restrict__ Hi, __nv_bfloat16* __restrict__ Lo)
{
    int net = blockIdx.y;
    int row = blockIdx.x;
    int t = threadIdx.x;
    const float* g = SEL3(net, g0, g1, g2);
    size_t off = (size_t)net * ASTR + (size_t)row * Uc;

    const float4* x4 = (const float4*)(X + off);
    float4 xv = x4[t];
    float ss = xv.x * xv.x + xv.y * xv.y + xv.z * xv.z + xv.w * xv.w;
    #pragma unroll
    for (int o = 16; o; o >>= 1) ss += __shfl_xor_sync(0xffffffffu, ss, o);
    __shared__ float sh[8];
    if ((t & 31) == 0) sh[t >> 5] = ss;
    __syncthreads();
    if (t < 32) {
        float v = (t < 8) ? sh[t] : 0.f;
        #pragma unroll
        for (int o = 4; o; o >>= 1) v += __shfl_xor_sync(0xffffffffu, v, o);
        if (t == 0) sh[0] = v;
    }
    __syncthreads();
    float r = rsqrtf(sh[0] * (1.0f / (float)Uc) + 1e-6f);
    float4 gv = ((const float4*)g)[t];
    float4 o;
    o.x = silu_f(xv.x * r * gv.x);
    o.y = silu_f(xv.y * r * gv.y);
    o.z = silu_f(xv.z * r * gv.z);
    o.w = silu_f(xv.w * r * gv.w);
    __nv_bfloat16 hx, hy, hz, hw, lx, ly, lz, lw;
    split1(o.x, hx, lx); split1(o.y, hy, ly);
    split1(o.z, hz, lz); split1(o.w, hw, lw);
    __nv_bfloat162 h0(hx, hy), h1(hz, hw), l0(lx, ly), l1(lz, lw);
    uint2 hp, lp;
    hp.x = *(uint32_t*)&h0; hp.y = *(uint32_t*)&h1;
    lp.x = *(uint32_t*)&l0; lp.y = *(uint32_t*)&l1;
    ((uint2*)(Hi + off))[t] = hp;
    ((uint2*)(Lo + off))[t] = lp;
}

// ---------------------------------------------------------------------------
// symexp bins
// ---------------------------------------------------------------------------
__device__ __forceinline__ float bin_val(int i) {
    float u = -20.0f + (40.0f / 254.0f) * (float)i;
    return copysignf(expm1f(fabsf(u)), u);
}

// ---------------------------------------------------------------------------
// slow_mean
// ---------------------------------------------------------------------------
__global__ __launch_bounds__(256) void slowmean_kernel(
    const float* __restrict__ slog, float* __restrict__ smean)
{
    __shared__ float sred[8];
    __shared__ double dden[8], dnum[8];
    int row = blockIdx.x, tid = threadIdx.x;
    float lg = -3.4e38f, bn = 0.f;
    if (tid < NBc) {
        lg = slog[(size_t)row * NBc + tid];
        bn = bin_val(tid);
    }
    float m = lg;
    #pragma unroll
    for (int o = 16; o; o >>= 1) m = fmaxf(m, __shfl_xor_sync(0xffffffffu, m, o));
    if ((tid & 31) == 0) sred[tid >> 5] = m;
    __syncthreads();
    if (tid < 32) {
        float v = (tid < 8) ? sred[tid] : -3.4e38f;
        #pragma unroll
        for (int o = 4; o; o >>= 1) v = fmaxf(v, __shfl_xor_sync(0xffffffffu, v, o));
        if (tid == 0) sred[0] = v;
    }
    __syncthreads();
    float M = sred[0];
    float e = (tid < NBc) ? expf(lg - M) : 0.f;
    double den = (double)e;
    double num = (double)e * (double)bn;
    #pragma unroll
    for (int o = 16; o; o >>= 1) {
        den += __shfl_xor_sync(0xffffffffu, den, o);
        num += __shfl_xor_sync(0xffffffffu, num, o);
    }
    if ((tid & 31) == 0) { dden[tid >> 5] = den; dnum[tid >> 5] = num; }
    __syncthreads();
    if (tid == 0) {
        double D = 0, Nn = 0;
        #pragma unroll
        for (int i = 0; i < 8; i++) { D += dden[i]; Nn += dnum[i]; }
        smean[row] = (float)(Nn / D);
    }
}

// ---------------------------------------------------------------------------
// lambda-return scan
// ---------------------------------------------------------------------------
__global__ void lamret_kernel(
    const float* __restrict__ reward, const float* __restrict__ cont,
    const float* __restrict__ smean, float* __restrict__ ret, float* __restrict__ wgt)
{
    int b = threadIdx.x;
    if (b >= Bc) return;
    float acc = 1.f;
    for (int t = 0; t < TM1; t++) {
        acc *= cont[b * Tc + t];
        wgt[b * TM1 + t] = acc;
    }
    float r = smean[b * Tc + (Tc - 1)];
    for (int t = TM1 - 1; t >= 0; t--) {
        float live = cont[b * Tc + t + 1];
        float interm = reward[b * Tc + t + 1] + (1.f - LAM_C) * live * smean[b * Tc + t + 1];
        r = interm + live * LAM_C * r;
        ret[b * TM1 + t] = r;
    }
}

// ---------------------------------------------------------------------------
// percentile via bitonic sort
// ---------------------------------------------------------------------------
__global__ void percentile_kernel(const float* __restrict__ ret, float* __restrict__ scale)
{
    extern __shared__ float s[];
    const int PAD = 32768;
    for (int i = threadIdx.x; i < PAD; i += blockDim.x)
        s[i] = (i < NLOSS) ? ret[i] : 3.4e38f;
    __syncthreads();
    for (int ksz = 2; ksz <= PAD; ksz <<= 1) {
        for (int j = ksz >> 1; j > 0; j >>= 1) {
            for (int a = threadIdx.x; a < PAD; a += blockDim.x) {
                int p = a ^ j;
                if (p > a) {
                    bool asc = ((a & ksz) == 0);
                    float x = s[a], y = s[p];
                    if ((x > y) == asc) { s[a] = y; s[p] = x; }
                }
            }
            __syncthreads();
        }
    }
    if (threadIdx.x == 0) {
        double p5 = 0.05 * (double)(NLOSS - 1);
        double p95 = 0.95 * (double)(NLOSS - 1);
        int i5 = (int)p5, i95 = (int)p95;
        float f5 = (float)(p5 - i5), f95 = (float)(p95 - i95);
        float lo = s[i5] + f5 * (s[i5 + 1] - s[i5]);
        float hi = s[i95] + f95 * (s[i95 + 1] - s[i95]);
        scale[0] = lo;
        scale[1] = hi;
        scale[2] = fmaxf(hi - lo, 1.0f);
    }
}

// ---------------------------------------------------------------------------
// per-token loss
// ---------------------------------------------------------------------------
__device__ __forceinline__ float twohot_nll(const float* svl, const float* sbins,
                                            float logZ, float y)
{
    y = fminf(fmaxf(y, sbins[0]), sbins[NBc - 1]);
    int lo = 0, hi = NBc - 1;
    while (hi > lo) {
        int mid = (lo + hi) >> 1;
        if (sbins[mid] >= y) hi = mid; else lo = mid + 1;
    }
    int k = hi - 1;
    if (k < 0) k = 0;
    if (k > NBc - 2) k = NBc - 2;
    float bl = sbins[k], bh = sbins[k + 1];
    float w = (y - bl) / (bh - bl);
    w = fminf(fmaxf(w, 0.f), 1.f);
    float l0 = svl[k] - logZ, l1 = svl[k + 1] - logZ;
    return -((1.f - w) * l0 + w * l1);
}

__global__ __launch_bounds__(256) void loss_kernel(
    const float* __restrict__ vlog, const float* __restrict__ plog,
    const float* __restrict__ smean, const float* __restrict__ ret,
    const float* __restrict__ wgt, const int* __restrict__ act,
    const float* __restrict__ scale, float* __restrict__ loss)
{
    __shared__ float sbins[NBc];
    __shared__ float svl[NBc];
    __shared__ float sred[8];
    __shared__ float sres[4];

    int i = blockIdx.x;
    int b = i / TM1, t = i - b * TM1;
    int row = b * Tc + t;
    int tid = threadIdx.x;

    if (tid < NBc) {
        sbins[tid] = bin_val(tid);
        svl[tid] = vlog[(size_t)row * NBc + tid];
    }
    __syncthreads();

    float v = (tid < NBc) ? svl[tid] : -3.4e38f;
    #pragma unroll
    for (int o = 16; o; o >>= 1) v = fmaxf(v, __shfl_xor_sync(0xffffffffu, v, o));
    if ((tid & 31) == 0) sred[tid >> 5] = v;
    __syncthreads();
    if (tid < 32) {
        float m = (tid < 8) ? sred[tid] : -3.4e38f;
        #pragma unroll
        for (int o = 4; o; o >>= 1) m = fmaxf(m, __shfl_xor_sync(0xffffffffu, m, o));
        if (tid == 0) sres[0] = m;
    }
    __syncthreads();
    float M = sres[0];
    float e = (tid < NBc) ? expf(svl[tid] - M) : 0.f;
    #pragma unroll
    for (int o = 16; o; o >>= 1) e += __shfl_xor_sync(0xffffffffu, e, o);
    if ((tid & 31) == 0) sred[tid >> 5] = e;
    __syncthreads();
    if (tid < 32) {
        float s = (tid < 8) ? sred[tid] : 0.f;
        #pragma unroll
        for (int o = 4; o; o >>= 1) s += __shfl_xor_sync(0xffffffffu, s, o);
        if (tid == 0) sres[0] = M + logf(s);
    }
    __syncthreads();
    float logZ = sres[0];

    if (tid < 32) {
        float p0 = plog[(size_t)row * Ac + tid];
        float p1 = plog[(size_t)row * Ac + tid + 32];
        float m = fmaxf(p0, p1);
        #pragma unroll
        for (int o = 16; o; o >>= 1) m = fmaxf(m, __shfl_xor_sync(0xffffffffu, m, o));
        float e0 = expf(p0 - m), e1 = expf(p1 - m);
        float s = e0 + e1;
        #pragma unroll
        for (int o = 16; o; o >>= 1) s += __shfl_xor_sync(0xffffffffu, s, o);
        float inv = 1.0f / s;
        float pr0 = 0.99f * e0 * inv + UNIMIX_A;
        float pr1 = 0.99f * e1 * inv + UNIMIX_A;
        float lp0 = logf(pr0), lp1 = logf(pr1);
        float entp = -(pr0 * lp0 + pr1 * lp1);
        #pragma unroll
        for (int o = 16; o; o >>= 1) entp += __shfl_xor_sync(0xffffffffu, entp, o);
        int a = act[row];
        float lpi = (a == tid) ? lp0 : ((a == tid + 32) ? lp1 : 0.f);
        #pragma unroll
        for (int o = 16; o; o >>= 1) lpi += __shfl_xor_sync(0xffffffffu, lpi, o);
        if (tid == 0) { sres[1] = entp; sres[2] = lpi; }
    }
    __syncthreads();

    if (tid == 0) {
        float reti = ret[i];
        float sm = smean[row];
        float rscale = scale[2];
        float adv = (reti - sm) / rscale;
        float wt = wgt[i];
        float pl = wt * -(sres[2] * adv + ACTENT_C * sres[1]);
        float vl = twohot_nll(svl, sbins, logZ, reti) + twohot_nll(svl, sbins, logZ, sm);
        loss[i] = pl + wt * vl;
    }
}

// ---------------------------------------------------------------------------
// final reduction
// ---------------------------------------------------------------------------
__global__ __launch_bounds__(1024) void reduce_kernel(
    const float* __restrict__ loss, float* __restrict__ out)
{
    __shared__ double sd[32];
    double s = 0.0;
    for (int i = threadIdx.x; i < NLOSS; i += 1024) s += (double)loss[i];
    #pragma unroll
    for (int o = 16; o; o >>= 1) s += __shfl_xor_sync(0xffffffffu, s, o);
    if ((threadIdx.x & 31) == 0) sd[threadIdx.x >> 5] = s;
    __syncthreads();
    if (threadIdx.x == 0) {
        double tot = 0.0;
        #pragma unroll
        for (int w = 0; w < 32; w++) tot += sd[w];
        out[0] = (float)(tot / (double)NLOSS);
    }
}

// ---------------------------------------------------------------------------
// host
// ---------------------------------------------------------------------------
extern "C" void kernel_launch(void* const* d_in, const int* in_sizes, int n_in,
                              void* d_out, int out_size)
{
    const float* feat   = (const float*)d_in[0];
    const float* reward = (const float*)d_in[1];
    const float* cont   = (const float*)d_in[2];
    const int*   act    = (const int*)  d_in[3];
    const float* pW_in  = (const float*)d_in[4];
    const float* pW_hid = (const float*)d_in[5];
    const float* p_gn   = (const float*)d_in[6];
    const float* pHw    = (const float*)d_in[7];
    const float* pHb    = (const float*)d_in[8];
    const float* vW_in  = (const float*)d_in[9];
    const float* vW_hid = (const float*)d_in[10];
    const float* v_gn   = (const float*)d_in[11];
    const float* vHw    = (const float*)d_in[12];
    const float* vHb    = (const float*)d_in[13];
    const float* sW_in  = (const float*)d_in[14];
    const float* sW_hid = (const float*)d_in[15];
    const float* s_gn   = (const float*)d_in[16];
    const float* sHw    = (const float*)d_in[17];
    const float* sHb    = (const float*)d_in[18];

    float *h0, *vslog, *plg, *smean, *ret, *wgt, *scale, *loss;
    __nv_bfloat16 *fhi, *flo, *a_hi, *a_lo, *w_hi, *w_lo;
    __nv_bfloat16 *hvs_hi, *hvs_lo, *hp_hi, *hp_lo;
    cudaGetSymbolAddress((void**)&h0, g_h0);
    cudaGetSymbolAddress((void**)&fhi, g_fhi);
    cudaGetSymbolAddress((void**)&flo, g_flo);
    cudaGetSymbolAddress((void**)&a_hi, g_a_hi);
    cudaGetSymbolAddress((void**)&a_lo, g_a_lo);
    cudaGetSymbolAddress((void**)&vslog, g_vslog);
    cudaGetSymbolAddress((void**)&plg, g_plog);
    cudaGetSymbolAddress((void**)&smean, g_smean);
    cudaGetSymbolAddress((void**)&ret, g_ret);
    cudaGetSymbolAddress((void**)&wgt, g_wgt);
    cudaGetSymbolAddress((void**)&scale, g_scale);
    cudaGetSymbolAddress((void**)&loss, g_loss);
    cudaGetSymbolAddress((void**)&w_hi, g_w_hi);
    cudaGetSymbolAddress((void**)&w_lo, g_w_lo);
    cudaGetSymbolAddress((void**)&hvs_hi, g_hvs_hi);
    cudaGetSymbolAddress((void**)&hvs_lo, g_hvs_lo);
    cudaGetSymbolAddress((void**)&hp_hi, g_hp_hi);
    cudaGetSymbolAddress((void**)&hp_lo, g_hp_lo);

    float* vlog = vslog;
    float* slog = vslog + LSTR;

    cudaFuncSetAttribute(tc_gemm, cudaFuncAttributeMaxDynamicSharedMemorySize, SMEM_B);
    cudaFuncSetAttribute(percentile_kernel,
                         cudaFuncAttributeMaxDynamicSharedMemorySize, 131072);

    dim3 tb(32, 8);
    // prep: 0=wt15, 1-3=head splits, 4=act split, 5=layer0 GEMM (ncu -s 5)
    split_wt15_kernel<<<dim3(32, 32, 15), tb>>>(
        vW_in, sW_in, pW_in, vW_hid, sW_hid, pW_hid, w_hi, w_lo);
    split_wt_kernel<<<dim3(32, 8), tb>>>(vHw, hvs_hi, hvs_lo, NBc);
    split_wt_kernel<<<dim3(32, 8), tb>>>(sHw, hvs_hi + HSTR, hvs_lo + HSTR, NBc);
    split_wt_kernel<<<dim3(32, 2), tb>>>(pHw, hp_hi, hp_lo, Ac);
    split_act_kernel<<<NTOK, 256>>>(feat, fhi, flo);

    // 5 fused layer GEMMs (z = net) + fused rmsnorm
    for (int l = 0; l < 5; l++) {
        const __nv_bfloat16* Ah = (l == 0) ? fhi : a_hi;
        const __nv_bfloat16* Al = (l == 0) ? flo : a_lo;
        size_t aStr = (l == 0) ? 0 : ASTR;
        tc_gemm<<<dim3(NTOK / 128, 8, 3), 256, SMEM_B>>>(
            Ah, Al, aStr,
            w_hi + (size_t)l * Uc * Uc, w_lo + (size_t)l * Uc * Uc, WSTR,
            nullptr, nullptr, h0, ASTR, Uc);
        rms3_kernel<<<dim3(NTOK, 3), 256>>>(
            h0, v_gn + (size_t)l * Uc, s_gn + (size_t)l * Uc, p_gn + (size_t)l * Uc,
            a_hi, a_lo);
    }

    // heads: v+s fused (z=2, Mout=255), p separate (Mout=64)
    tc_gemm<<<dim3(NTOK / 128, 2, 2), 256, SMEM_B>>>(
        a_hi, a_lo, ASTR, hvs_hi, hvs_lo, HSTR,
        vHb, sHb, vslog, LSTR, NBc);
    tc_gemm<<<dim3(NTOK / 128, 1, 1), 256, SMEM_B>>>(
        a_hi + 2 * ASTR, a_lo + 2 * ASTR, 0, hp_hi, hp_lo, 0,
        pHb, nullptr, plg, 0, Ac);

    slowmean_kernel<<<NTOK, 256>>>(slog, smean);
    lamret_kernel<<<1, 64>>>(reward, cont, smean, ret, wgt);
    percentile_kernel<<<1, 1024, 131072>>>(ret, scale);
    loss_kernel<<<NLOSS, 256>>>(vlog, plg, smean, ret, wgt, act, scale, loss);
    reduce_kernel<<<1, 1024>>>(loss, (float*)d_out);
}

// round 9
// speedup vs baseline: 1.5139x; 1.0024x over previous
#include <cuda_runtime.h>
#include <cuda_bf16.h>
#include <math.h>
#include <stdint.h>

// ---------------------------------------------------------------------------
// Problem constants
// ---------------------------------------------------------------------------
#define Bc    64
#define Tc    334
#define Fc    1024
#define Uc    1024
#define Ac    64
#define NBc   255
#define NTOK  (Bc * Tc)        // 21376 = 167 * 128
#define TM1   (Tc - 1)         // 333
#define NLOSS (Bc * TM1)       // 21312
#define LAM_C     0.95f
#define ACTENT_C  3e-4f
#define UNIMIX_A  0.00015625f  // 0.01 / 64
#define NCH   32               // K chunks of 32 (K = 1024)

// smem tile: 128 rows x 32 bf16, row stride 40 bf16 (80 B) -> conflict-free ldmatrix
#define TSTRIDE 40
#define TILE_B  (128 * TSTRIDE * 2)   // 10240 bytes
#define STAGE_B (4 * TILE_B)          // 40960 bytes (Ahi,Alo,Bhi,Blo)
#define NSTAGE  2
#define SMEM_B  (NSTAGE * STAGE_B)    // 81920 bytes -> 2 CTAs/SM

// net strides (elements)
#define ASTR ((size_t)NTOK * Uc)          // activation buffers
#define WSTR ((size_t)5 * 1024 * 1024)    // square-weight buffers
#define HSTR ((size_t)256 * 1024)         // v/s head weight buffers
#define LSTR ((size_t)NTOK * NBc)         // v/s logits

// ---------------------------------------------------------------------------
// Device scratch — single symbols, net index via stride
// ---------------------------------------------------------------------------
__device__ float g_h0[3 * ASTR];
__device__ __nv_bfloat16 g_fhi[ASTR];
__device__ __nv_bfloat16 g_flo[ASTR];
__device__ __nv_bfloat16 g_a_hi[3 * ASTR];
__device__ __nv_bfloat16 g_a_lo[3 * ASTR];
__device__ float g_vslog[2 * LSTR];          // [0]=vlog, [1]=slog
__device__ float g_plog[(size_t)NTOK * Ac];
__device__ float g_smean[NTOK];
__device__ float g_ret[NLOSS];
__device__ float g_wgt[NLOSS];
__device__ float g_scale[4];
__device__ float g_loss[NLOSS];
// split K-major weights (bf16 hi/lo). Head pad rows never written -> stay 0.
__device__ __nv_bfloat16 g_w_hi[3 * WSTR];
__device__ __nv_bfloat16 g_w_lo[3 * WSTR];
__device__ __nv_bfloat16 g_hvs_hi[2 * HSTR];
__device__ __nv_bfloat16 g_hvs_lo[2 * HSTR];
__device__ __nv_bfloat16 g_hp_hi[128 * 1024];
__device__ __nv_bfloat16 g_hp_lo[128 * 1024];

// ---------------------------------------------------------------------------
// helpers
// ---------------------------------------------------------------------------
__device__ __forceinline__ uint32_t smem_u32(const void* p) {
    uint32_t a;
    asm("{ .reg .u64 t; cvta.to.shared.u64 t, %1; cvt.u32.u64 %0, t; }" : "=r"(a) : "l"(p));
    return a;
}
__device__ __forceinline__ void ldm_x4(uint32_t* f, uint32_t addr) {
    asm volatile("ldmatrix.sync.aligned.m8n8.x4.shared.b16 {%0,%1,%2,%3}, [%4];"
                 : "=r"(f[0]), "=r"(f[1]), "=r"(f[2]), "=r"(f[3]) : "r"(addr));
}
__device__ __forceinline__ void mma_bf16(float* c, const uint32_t* a,
                                         uint32_t b0, uint32_t b1) {
    asm volatile(
        "mma.sync.aligned.m16n8k16.row.col.f32.bf16.bf16.f32 "
        "{%0,%1,%2,%3}, {%4,%5,%6,%7}, {%8,%9}, {%0,%1,%2,%3};"
        : "+f"(c[0]), "+f"(c[1]), "+f"(c[2]), "+f"(c[3])
        : "r"(a[0]), "r"(a[1]), "r"(a[2]), "r"(a[3]), "r"(b0), "r"(b1));
}
__device__ __forceinline__ void cp16(uint32_t dst, const void* src) {
    asm volatile("cp.async.ca.shared.global [%0], [%1], 16;" :: "r"(dst), "l"(src));
}
__device__ __forceinline__ void cp_commit() {
    asm volatile("cp.async.commit_group;" ::: "memory");
}
__device__ __forceinline__ void cp_wait1() {
    asm volatile("cp.async.wait_group 1;" ::: "memory");
}
__device__ __forceinline__ void split1(float v, __nv_bfloat16& h, __nv_bfloat16& l) {
    h = __float2bfloat16(v);
    l = __float2bfloat16(v - __bfloat162float(h));
}
#define SEL3(z, a, b, cc) ((z) == 0 ? (a) : (z) == 1 ? (b) : (cc))

// ---------------------------------------------------------------------------
// bf16x3-split tensor-core GEMM (multi-problem via blockIdx.z + strides).
// Inner loop: interleaved LDSM/MMA (de-phased) — single change vs R8.
// ---------------------------------------------------------------------------
__global__ __launch_bounds__(256, 2) void tc_gemm(
    const __nv_bfloat16* __restrict__ Ahi_, const __nv_bfloat16* __restrict__ Alo_,
    size_t aStr,
    const __nv_bfloat16* __restrict__ Bhi_, const __nv_bfloat16* __restrict__ Blo_,
    size_t bStr,
    const float* bias0, const float* bias1,
    float* C_, size_t cStr, int Mout)
{
    extern __shared__ char smem[];
    const uint32_t sb = smem_u32(smem);
    const int z = blockIdx.z;
    const __nv_bfloat16* __restrict__ Ahi = Ahi_ + (size_t)z * aStr;
    const __nv_bfloat16* __restrict__ Alo = Alo_ + (size_t)z * aStr;
    const __nv_bfloat16* __restrict__ Bhi = Bhi_ + (size_t)z * bStr;
    const __nv_bfloat16* __restrict__ Blo = Blo_ + (size_t)z * bStr;
    const float* bias = (z == 0) ? bias0 : bias1;
    float* __restrict__ C = C_ + (size_t)z * cStr;

    const int tid = threadIdx.x;
    const int lane = tid & 31;
    const int warp = tid >> 5;
    const int brow = blockIdx.x * 128;
    const int bcol = blockIdx.y * 128;

    const int m0w = (warp >> 1) * 32;
    const int n0w = (warp & 1) * 64;
    const int lrow = lane & 15;
    const int lcol8 = (lane >> 4) << 3;

    float c[2][8][4];
    #pragma unroll
    for (int i = 0; i < 2; i++)
        #pragma unroll
        for (int j = 0; j < 8; j++)
            #pragma unroll
            for (int q = 0; q < 4; q++) c[i][j][q] = 0.f;

    auto issue = [&](int stage, int ch) {
        const int k0 = ch * 32;
        #pragma unroll
        for (int j = 0; j < 8; j++) {
            int gid = tid + 256 * j;
            int tl = gid >> 9;           // 0=Ahi 1=Alo 2=Bhi 3=Blo
            int t = gid & 511;
            int r = t >> 2, a = t & 3;
            const __nv_bfloat16* base =
                (tl == 0) ? Ahi : (tl == 1) ? Alo : (tl == 2) ? Bhi : Blo;
            int grow = ((tl < 2) ? brow : bcol) + r;
            const __nv_bfloat16* src = base + (size_t)grow * 1024 + k0 + a * 8;
            uint32_t dst = sb + (uint32_t)stage * STAGE_B + (uint32_t)tl * TILE_B
                         + (uint32_t)(r * 80 + a * 16);
            cp16(dst, src);
        }
        cp_commit();
    };

    issue(0, 0);
    issue(1, 1);

    for (int ch = 0; ch < NCH; ch++) {
        cp_wait1();
        __syncthreads();

        const uint32_t base = sb + (uint32_t)(ch & 1) * STAGE_B;
        #pragma unroll
        for (int ss = 0; ss < 2; ss++) {
            const int kk = ss * 16;
            uint32_t aHi[2][4], aLo[2][4], bH[4][4];
            uint32_t ar0 = base + (uint32_t)((m0w + lrow) * TSTRIDE + kk + lcol8) * 2;
            uint32_t ar1 = base + (uint32_t)((m0w + 16 + lrow) * TSTRIDE + kk + lcol8) * 2;
            uint32_t brb = base + 2 * TILE_B +
                           (uint32_t)((n0w + lrow) * TSTRIDE + kk + lcol8) * 2;
            const uint32_t gstep = (uint32_t)(16 * TSTRIDE) * 2;

            // A-hi + first B-hi fragment
            ldm_x4(aHi[0], ar0);
            ldm_x4(aHi[1], ar1);
            ldm_x4(bH[0], brb);
            // pass 1: Ahi x Bhi, prefetching bH[g+1] inside the MMA stream
            #pragma unroll
            for (int g = 0; g < 4; g++) {
                if (g < 3) ldm_x4(bH[g + 1], brb + (uint32_t)(g + 1) * gstep);
                mma_bf16(c[0][2 * g],     aHi[0], bH[g][0], bH[g][2]);
                mma_bf16(c[0][2 * g + 1], aHi[0], bH[g][1], bH[g][3]);
                mma_bf16(c[1][2 * g],     aHi[1], bH[g][0], bH[g][2]);
                mma_bf16(c[1][2 * g + 1], aHi[1], bH[g][1], bH[g][3]);
            }
            // A-lo fragments (latency covered by pass-1 MMA backlog)
            ldm_x4(aLo[0], ar0 + TILE_B);
            ldm_x4(aLo[1], ar1 + TILE_B);
            // pass 2: Alo x Bhi (pure MMA)
            #pragma unroll
            for (int g = 0; g < 4; g++) {
                mma_bf16(c[0][2 * g],     aLo[0], bH[g][0], bH[g][2]);
                mma_bf16(c[0][2 * g + 1], aLo[0], bH[g][1], bH[g][3]);
                mma_bf16(c[1][2 * g],     aLo[1], bH[g][0], bH[g][2]);
                mma_bf16(c[1][2 * g + 1], aLo[1], bH[g][1], bH[g][3]);
            }
            // pass 3: Ahi x Blo (bL JIT inside the MMA stream)
            #pragma unroll
            for (int g = 0; g < 4; g++) {
                uint32_t bL[4];
                ldm_x4(bL, brb + TILE_B + (uint32_t)g * gstep);
                mma_bf16(c[0][2 * g],     aHi[0], bL[0], bL[2]);
                mma_bf16(c[0][2 * g + 1], aHi[0], bL[1], bL[3]);
                mma_bf16(c[1][2 * g],     aHi[1], bL[0], bL[2]);
                mma_bf16(c[1][2 * g + 1], aHi[1], bL[1], bL[3]);
            }
        }
        __syncthreads();
        if (ch + NSTAGE < NCH) issue(ch & 1, ch + NSTAGE);
        else cp_commit();
    }

    // epilogue
    const int r = lane >> 2;
    const int cc = 2 * (lane & 3);
    #pragma unroll
    for (int i = 0; i < 2; i++) {
        int rowb = brow + m0w + i * 16;
        #pragma unroll
        for (int j = 0; j < 8; j++) {
            int col = bcol + n0w + j * 8 + cc;
            float b0 = 0.f, b1 = 0.f;
            if (bias) {
                if (col < Mout) b0 = bias[col];
                if (col + 1 < Mout) b1 = bias[col + 1];
            }
            float* p0 = C + (size_t)(rowb + r) * Mout + col;
            float* p1 = C + (size_t)(rowb + r + 8) * Mout + col;
            if (col + 1 < Mout) {
                p0[0] = c[i][j][0] + b0; p0[1] = c[i][j][1] + b1;
                p1[0] = c[i][j][2] + b0; p1[1] = c[i][j][3] + b1;
            } else if (col < Mout) {
                p0[0] = c[i][j][0] + b0;
                p1[0] = c[i][j][2] + b0;
            }
        }
    }
}

// ---------------------------------------------------------------------------
// all 15 square weight transpose+splits in one launch (z = net*5 + layer)
// ---------------------------------------------------------------------------
__global__ __launch_bounds__(256) void split_wt15_kernel(
    const float* Win0, const float* Win1, const float* Win2,
    const float* Whid0, const float* Whid1, const float* Whid2,
    __nv_bfloat16* Whi, __nv_bfloat16* Wlo)
{
    __shared__ float t[32][33];
    int z = blockIdx.z;
    int net = z / 5, layer = z % 5;
    const float* Win  = SEL3(net, Win0, Win1, Win2);
    const float* Whid = SEL3(net, Whid0, Whid1, Whid2);
    const float* W = (layer == 0) ? Win : (Whid + (size_t)(layer - 1) * Uc * Uc);
    __nv_bfloat16* dhi = Whi + (size_t)net * WSTR + (size_t)layer * Uc * Uc;
    __nv_bfloat16* dlo = Wlo + (size_t)net * WSTR + (size_t)layer * Uc * Uc;
    int k0 = blockIdx.x * 32, m0 = blockIdx.y * 32;
    int x = threadIdx.x, y = threadIdx.y;   // 32 x 8
    #pragma unroll
    for (int j = 0; j < 32; j += 8)
        t[y + j][x] = W[(size_t)(k0 + y + j) * Uc + m0 + x];
    __syncthreads();
    #pragma unroll
    for (int j = 0; j < 32; j += 8) {
        int m = m0 + y + j;
        float v = t[x][y + j];
        __nv_bfloat16 h, l;
        split1(v, h, l);
        dhi[(size_t)m * 1024 + k0 + x] = h;
        dlo[(size_t)m * 1024 + k0 + x] = l;
    }
}

// head transpose + split: W[1024, M] -> [M,1024]
__global__ __launch_bounds__(256) void split_wt_kernel(
    const float* __restrict__ W, __nv_bfloat16* __restrict__ Whi,
    __nv_bfloat16* __restrict__ Wlo, int M)
{
    __shared__ float t[32][33];
    int k0 = blockIdx.x * 32, m0 = blockIdx.y * 32;
    int x = threadIdx.x, y = threadIdx.y;
    #pragma unroll
    for (int j = 0; j < 32; j += 8) {
        int m = m0 + x;
        if (m < M) t[y + j][x] = W[(size_t)(k0 + y + j) * M + m];
    }
    __syncthreads();
    #pragma unroll
    for (int j = 0; j < 32; j += 8) {
        int m = m0 + y + j;
        if (m < M) {
            float v = t[x][y + j];
            __nv_bfloat16 h, l;
            split1(v, h, l);
            Whi[(size_t)m * 1024 + k0 + x] = h;
            Wlo[(size_t)m * 1024 + k0 + x] = l;
        }
    }
}

// ---------------------------------------------------------------------------
// feat split
// ---------------------------------------------------------------------------
__global__ __launch_bounds__(256) void split_act_kernel(
    const float* __restrict__ X, __nv_bfloat16* __restrict__ Hi,
    __nv_bfloat16* __restrict__ Lo)
{
    size_t i = (size_t)blockIdx.x * 256 + threadIdx.x;
    float4 v = ((const float4*)X)[i];
    __nv_bfloat16 hx, hy, hz, hw, lx, ly, lz, lw;
    split1(v.x, hx, lx); split1(v.y, hy, ly);
    split1(v.z, hz, lz); split1(v.w, hw, lw);
    __nv_bfloat162 h0(hx, hy), h1(hz, hw), l0(lx, ly), l1(lz, lw);
    uint2 hp, lp;
    hp.x = *(uint32_t*)&h0; hp.y = *(uint32_t*)&h1;
    lp.x = *(uint32_t*)&l0; lp.y = *(uint32_t*)&l1;
    ((uint2*)Hi)[i] = hp;
    ((uint2*)Lo)[i] = lp;
}

// ---------------------------------------------------------------------------
// fused rmsnorm + silu + split for 3 nets (blockIdx.y = net, strided buffers)
// ---------------------------------------------------------------------------
__device__ __forceinline__ float silu_f(float z) { return z / (1.f + expf(-z)); }

__global__ __launch_bounds__(256) void rms3_kernel(
    const float* __restrict__ X,
    const float* g0, const float* g1, const float* g2,
    __nv_bfloat16* __restrict__ Hi, __nv_bfloat16* __restrict__ Lo)
{
    int net = blockIdx.y;
    int row = blockIdx.x;
    int t = threadIdx.x;
    const float* g = SEL3(net, g0, g1, g2);
    size_t off = (size_t)net * ASTR + (size_t)row * Uc;

    const float4* x4 = (const float4*)(X + off);
    float4 xv = x4[t];
    float ss = xv.x * xv.x + xv.y * xv.y + xv.z * xv.z + xv.w * xv.w;
    #pragma unroll
    for (int o = 16; o; o >>= 1) ss += __shfl_xor_sync(0xffffffffu, ss, o);
    __shared__ float sh[8];
    if ((t & 31) == 0) sh[t >> 5] = ss;
    __syncthreads();
    if (t < 32) {
        float v = (t < 8) ? sh[t] : 0.f;
        #pragma unroll
        for (int o = 4; o; o >>= 1) v += __shfl_xor_sync(0xffffffffu, v, o);
        if (t == 0) sh[0] = v;
    }
    __syncthreads();
    float r = rsqrtf(sh[0] * (1.0f / (float)Uc) + 1e-6f);
    float4 gv = ((const float4*)g)[t];
    float4 o;
    o.x = silu_f(xv.x * r * gv.x);
    o.y = silu_f(xv.y * r * gv.y);
    o.z = silu_f(xv.z * r * gv.z);
    o.w = silu_f(xv.w * r * gv.w);
    __nv_bfloat16 hx, hy, hz, hw, lx, ly, lz, lw;
    split1(o.x, hx, lx); split1(o.y, hy, ly);
    split1(o.z, hz, lz); split1(o.w, hw, lw);
    __nv_bfloat162 h0(hx, hy), h1(hz, hw), l0(lx, ly), l1(lz, lw);
    uint2 hp, lp;
    hp.x = *(uint32_t*)&h0; hp.y = *(uint32_t*)&h1;
    lp.x = *(uint32_t*)&l0; lp.y = *(uint32_t*)&l1;
    ((uint2*)(Hi + off))[t] = hp;
    ((uint2*)(Lo + off))[t] = lp;
}

// ---------------------------------------------------------------------------
// symexp bins
// ---------------------------------------------------------------------------
__device__ __forceinline__ float bin_val(int i) {
    float u = -20.0f + (40.0f / 254.0f) * (float)i;
    return copysignf(expm1f(fabsf(u)), u);
}

// ---------------------------------------------------------------------------
// slow_mean
// ---------------------------------------------------------------------------
__global__ __launch_bounds__(256) void slowmean_kernel(
    const float* __restrict__ slog, float* __restrict__ smean)
{
    __shared__ float sred[8];
    __shared__ double dden[8], dnum[8];
    int row = blockIdx.x, tid = threadIdx.x;
    float lg = -3.4e38f, bn = 0.f;
    if (tid < NBc) {
        lg = slog[(size_t)row * NBc + tid];
        bn = bin_val(tid);
    }
    float m = lg;
    #pragma unroll
    for (int o = 16; o; o >>= 1) m = fmaxf(m, __shfl_xor_sync(0xffffffffu, m, o));
    if ((tid & 31) == 0) sred[tid >> 5] = m;
    __syncthreads();
    if (tid < 32) {
        float v = (tid < 8) ? sred[tid] : -3.4e38f;
        #pragma unroll
        for (int o = 4; o; o >>= 1) v = fmaxf(v, __shfl_xor_sync(0xffffffffu, v, o));
        if (tid == 0) sred[0] = v;
    }
    __syncthreads();
    float M = sred[0];
    float e = (tid < NBc) ? expf(lg - M) : 0.f;
    double den = (double)e;
    double num = (double)e * (double)bn;
    #pragma unroll
    for (int o = 16; o; o >>= 1) {
        den += __shfl_xor_sync(0xffffffffu, den, o);
        num += __shfl_xor_sync(0xffffffffu, num, o);
    }
    if ((tid & 31) == 0) { dden[tid >> 5] = den; dnum[tid >> 5] = num; }
    __syncthreads();
    if (tid == 0) {
        double D = 0, Nn = 0;
        #pragma unroll
        for (int i = 0; i < 8; i++) { D += dden[i]; Nn += dnum[i]; }
        smean[row] = (float)(Nn / D);
    }
}

// ---------------------------------------------------------------------------
// lambda-return scan
// ---------------------------------------------------------------------------
__global__ void lamret_kernel(
    const float* __restrict__ reward, const float* __restrict__ cont,
    const float* __restrict__ smean, float* __restrict__ ret, float* __restrict__ wgt)
{
    int b = threadIdx.x;
    if (b >= Bc) return;
    float acc = 1.f;
    for (int t = 0; t < TM1; t++) {
        acc *= cont[b * Tc + t];
        wgt[b * TM1 + t] = acc;
    }
    float r = smean[b * Tc + (Tc - 1)];
    for (int t = TM1 - 1; t >= 0; t--) {
        float live = cont[b * Tc + t + 1];
        float interm = reward[b * Tc + t + 1] + (1.f - LAM_C) * live * smean[b * Tc + t + 1];
        r = interm + live * LAM_C * r;
        ret[b * TM1 + t] = r;
    }
}

// ---------------------------------------------------------------------------
// percentile via bitonic sort
// ---------------------------------------------------------------------------
__global__ void percentile_kernel(const float* __restrict__ ret, float* __restrict__ scale)
{
    extern __shared__ float s[];
    const int PAD = 32768;
    for (int i = threadIdx.x; i < PAD; i += blockDim.x)
        s[i] = (i < NLOSS) ? ret[i] : 3.4e38f;
    __syncthreads();
    for (int ksz = 2; ksz <= PAD; ksz <<= 1) {
        for (int j = ksz >> 1; j > 0; j >>= 1) {
            for (int a = threadIdx.x; a < PAD; a += blockDim.x) {
                int p = a ^ j;
                if (p > a) {
                    bool asc = ((a & ksz) == 0);
                    float x = s[a], y = s[p];
                    if ((x > y) == asc) { s[a] = y; s[p] = x; }
                }
            }
            __syncthreads();
        }
    }
    if (threadIdx.x == 0) {
        double p5 = 0.05 * (double)(NLOSS - 1);
        double p95 = 0.95 * (double)(NLOSS - 1);
        int i5 = (int)p5, i95 = (int)p95;
        float f5 = (float)(p5 - i5), f95 = (float)(p95 - i95);
        float lo = s[i5] + f5 * (s[i5 + 1] - s[i5]);
        float hi = s[i95] + f95 * (s[i95 + 1] - s[i95]);
        scale[0] = lo;
        scale[1] = hi;
        scale[2] = fmaxf(hi - lo, 1.0f);
    }
}

// ---------------------------------------------------------------------------
// per-token loss
// ---------------------------------------------------------------------------
__device__ __forceinline__ float twohot_nll(const float* svl, const float* sbins,
                                            float logZ, float y)
{
    y = fminf(fmaxf(y, sbins[0]), sbins[NBc - 1]);
    int lo = 0, hi = NBc - 1;
    while (hi > lo) {
        int mid = (lo + hi) >> 1;
        if (sbins[mid] >= y) hi = mid; else lo = mid + 1;
    }
    int k = hi - 1;
    if (k < 0) k = 0;
    if (k > NBc - 2) k = NBc - 2;
    float bl = sbins[k], bh = sbins[k + 1];
    float w = (y - bl) / (bh - bl);
    w = fminf(fmaxf(w, 0.f), 1.f);
    float l0 = svl[k] - logZ, l1 = svl[k + 1] - logZ;
    return -((1.f - w) * l0 + w * l1);
}

__global__ __launch_bounds__(256) void loss_kernel(
    const float* __restrict__ vlog, const float* __restrict__ plog,
    const float* __restrict__ smean, const float* __restrict__ ret,
    const float* __restrict__ wgt, const int* __restrict__ act,
    const float* __restrict__ scale, float* __restrict__ loss)
{
    __shared__ float sbins[NBc];
    __shared__ float svl[NBc];
    __shared__ float sred[8];
    __shared__ float sres[4];

    int i = blockIdx.x;
    int b = i / TM1, t = i - b * TM1;
    int row = b * Tc + t;
    int tid = threadIdx.x;

    if (tid < NBc) {
        sbins[tid] = bin_val(tid);
        svl[tid] = vlog[(size_t)row * NBc + tid];
    }
    __syncthreads();

    float v = (tid < NBc) ? svl[tid] : -3.4e38f;
    #pragma unroll
    for (int o = 16; o; o >>= 1) v = fmaxf(v, __shfl_xor_sync(0xffffffffu, v, o));
    if ((tid & 31) == 0) sred[tid >> 5] = v;
    __syncthreads();
    if (tid < 32) {
        float m = (tid < 8) ? sred[tid] : -3.4e38f;
        #pragma unroll
        for (int o = 4; o; o >>= 1) m = fmaxf(m, __shfl_xor_sync(0xffffffffu, m, o));
        if (tid == 0) sres[0] = m;
    }
    __syncthreads();
    float M = sres[0];
    float e = (tid < NBc) ? expf(svl[tid] - M) : 0.f;
    #pragma unroll
    for (int o = 16; o; o >>= 1) e += __shfl_xor_sync(0xffffffffu, e, o);
    if ((tid & 31) == 0) sred[tid >> 5] = e;
    __syncthreads();
    if (tid < 32) {
        float s = (tid < 8) ? sred[tid] : 0.f;
        #pragma unroll
        for (int o = 4; o; o >>= 1) s += __shfl_xor_sync(0xffffffffu, s, o);
        if (tid == 0) sres[0] = M + logf(s);
    }
    __syncthreads();
    float logZ = sres[0];

    if (tid < 32) {
        float p0 = plog[(size_t)row * Ac + tid];
        float p1 = plog[(size_t)row * Ac + tid + 32];
        float m = fmaxf(p0, p1);
        #pragma unroll
        for (int o = 16; o; o >>= 1) m = fmaxf(m, __shfl_xor_sync(0xffffffffu, m, o));
        float e0 = expf(p0 - m), e1 = expf(p1 - m);
        float s = e0 + e1;
        #pragma unroll
        for (int o = 16; o; o >>= 1) s += __shfl_xor_sync(0xffffffffu, s, o);
        float inv = 1.0f / s;
        float pr0 = 0.99f * e0 * inv + UNIMIX_A;
        float pr1 = 0.99f * e1 * inv + UNIMIX_A;
        float lp0 = logf(pr0), lp1 = logf(pr1);
        float entp = -(pr0 * lp0 + pr1 * lp1);
        #pragma unroll
        for (int o = 16; o; o >>= 1) entp += __shfl_xor_sync(0xffffffffu, entp, o);
        int a = act[row];
        float lpi = (a == tid) ? lp0 : ((a == tid + 32) ? lp1 : 0.f);
        #pragma unroll
        for (int o = 16; o; o >>= 1) lpi += __shfl_xor_sync(0xffffffffu, lpi, o);
        if (tid == 0) { sres[1] = entp; sres[2] = lpi; }
    }
    __syncthreads();

    if (tid == 0) {
        float reti = ret[i];
        float sm = smean[row];
        float rscale = scale[2];
        float adv = (reti - sm) / rscale;
        float wt = wgt[i];
        float pl = wt * -(sres[2] * adv + ACTENT_C * sres[1]);
        float vl = twohot_nll(svl, sbins, logZ, reti) + twohot_nll(svl, sbins, logZ, sm);
        loss[i] = pl + wt * vl;
    }
}

// ---------------------------------------------------------------------------
// final reduction
// ---------------------------------------------------------------------------
__global__ __launch_bounds__(1024) void reduce_kernel(
    const float* __restrict__ loss, float* __restrict__ out)
{
    __shared__ double sd[32];
    double s = 0.0;
    for (int i = threadIdx.x; i < NLOSS; i += 1024) s += (double)loss[i];
    #pragma unroll
    for (int o = 16; o; o >>= 1) s += __shfl_xor_sync(0xffffffffu, s, o);
    if ((threadIdx.x & 31) == 0) sd[threadIdx.x >> 5] = s;
    __syncthreads();
    if (threadIdx.x == 0) {
        double tot = 0.0;
        #pragma unroll
        for (int w = 0; w < 32; w++) tot += sd[w];
        out[0] = (float)(tot / (double)NLOSS);
    }
}

// ---------------------------------------------------------------------------
// host
// ---------------------------------------------------------------------------
extern "C" void kernel_launch(void* const* d_in, const int* in_sizes, int n_in,
                              void* d_out, int out_size)
{
    const float* feat   = (const float*)d_in[0];
    const float* reward = (const float*)d_in[1];
    const float* cont   = (const float*)d_in[2];
    const int*   act    = (const int*)  d_in[3];
    const float* pW_in  = (const float*)d_in[4];
    const float* pW_hid = (const float*)d_in[5];
    const float* p_gn   = (const float*)d_in[6];
    const float* pHw    = (const float*)d_in[7];
    const float* pHb    = (const float*)d_in[8];
    const float* vW_in  = (const float*)d_in[9];
    const float* vW_hid = (const float*)d_in[10];
    const float* v_gn   = (const float*)d_in[11];
    const float* vHw    = (const float*)d_in[12];
    const float* vHb    = (const float*)d_in[13];
    const float* sW_in  = (const float*)d_in[14];
    const float* sW_hid = (const float*)d_in[15];
    const float* s_gn   = (const float*)d_in[16];
    const float* sHw    = (const float*)d_in[17];
    const float* sHb    = (const float*)d_in[18];

    float *h0, *vslog, *plg, *smean, *ret, *wgt, *scale, *loss;
    __nv_bfloat16 *fhi, *flo, *a_hi, *a_lo, *w_hi, *w_lo;
    __nv_bfloat16 *hvs_hi, *hvs_lo, *hp_hi, *hp_lo;
    cudaGetSymbolAddress((void**)&h0, g_h0);
    cudaGetSymbolAddress((void**)&fhi, g_fhi);
    cudaGetSymbolAddress((void**)&flo, g_flo);
    cudaGetSymbolAddress((void**)&a_hi, g_a_hi);
    cudaGetSymbolAddress((void**)&a_lo, g_a_lo);
    cudaGetSymbolAddress((void**)&vslog, g_vslog);
    cudaGetSymbolAddress((void**)&plg, g_plog);
    cudaGetSymbolAddress((void**)&smean, g_smean);
    cudaGetSymbolAddress((void**)&ret, g_ret);
    cudaGetSymbolAddress((void**)&wgt, g_wgt);
    cudaGetSymbolAddress((void**)&scale, g_scale);
    cudaGetSymbolAddress((void**)&loss, g_loss);
    cudaGetSymbolAddress((void**)&w_hi, g_w_hi);
    cudaGetSymbolAddress((void**)&w_lo, g_w_lo);
    cudaGetSymbolAddress((void**)&hvs_hi, g_hvs_hi);
    cudaGetSymbolAddress((void**)&hvs_lo, g_hvs_lo);
    cudaGetSymbolAddress((void**)&hp_hi, g_hp_hi);
    cudaGetSymbolAddress((void**)&hp_lo, g_hp_lo);

    float* vlog = vslog;
    float* slog = vslog + LSTR;

    cudaFuncSetAttribute(tc_gemm, cudaFuncAttributeMaxDynamicSharedMemorySize, SMEM_B);
    cudaFuncSetAttribute(percentile_kernel,
                         cudaFuncAttributeMaxDynamicSharedMemorySize, 131072);

    dim3 tb(32, 8);
    // prep: 0=wt15, 1-3=head splits, 4=act split, 5=layer0 GEMM (ncu -s 5)
    split_wt15_kernel<<<dim3(32, 32, 15), tb>>>(
        vW_in, sW_in, pW_in, vW_hid, sW_hid, pW_hid, w_hi, w_lo);
    split_wt_kernel<<<dim3(32, 8), tb>>>(vHw, hvs_hi, hvs_lo, NBc);
    split_wt_kernel<<<dim3(32, 8), tb>>>(sHw, hvs_hi + HSTR, hvs_lo + HSTR, NBc);
    split_wt_kernel<<<dim3(32, 2), tb>>>(pHw, hp_hi, hp_lo, Ac);
    split_act_kernel<<<NTOK, 256>>>(feat, fhi, flo);

    // 5 fused layer GEMMs (z = net) + fused rmsnorm
    for (int l = 0; l < 5; l++) {
        const __nv_bfloat16* Ah = (l == 0) ? fhi : a_hi;
        const __nv_bfloat16* Al = (l == 0) ? flo : a_lo;
        size_t aStr = (l == 0) ? 0 : ASTR;
        tc_gemm<<<dim3(NTOK / 128, 8, 3), 256, SMEM_B>>>(
            Ah, Al, aStr,
            w_hi + (size_t)l * Uc * Uc, w_lo + (size_t)l * Uc * Uc, WSTR,
            nullptr, nullptr, h0, ASTR, Uc);
        rms3_kernel<<<dim3(NTOK, 3), 256>>>(
            h0, v_gn + (size_t)l * Uc, s_gn + (size_t)l * Uc, p_gn + (size_t)l * Uc,
            a_hi, a_lo);
    }

    // heads: v+s fused (z=2, Mout=255), p separate (Mout=64)
    tc_gemm<<<dim3(NTOK / 128, 2, 2), 256, SMEM_B>>>(
        a_hi, a_lo, ASTR, hvs_hi, hvs_lo, HSTR,
        vHb, sHb, vslog, LSTR, NBc);
    tc_gemm<<<dim3(NTOK / 128, 1, 1), 256, SMEM_B>>>(
        a_hi + 2 * ASTR, a_lo + 2 * ASTR, 0, hp_hi, hp_lo, 0,
        pHb, nullptr, plg, 0, Ac);

    slowmean_kernel<<<NTOK, 256>>>(slog, smean);
    lamret_kernel<<<1, 64>>>(reward, cont, smean, ret, wgt);
    percentile_kernel<<<1, 1024, 131072>>>(ret, scale);
    loss_kernel<<<NLOSS, 256>>>(vlog, plg, smean, ret, wgt, act, scale, loss);
    reduce_kernel<<<1, 1024>>>(loss, (float*)d_out);
}